// round 5
// baseline (speedup 1.0000x reference)
#include <cuda_runtime.h>
#include <math.h>

// Problem constants
#define B_   8
#define S_   1024
#define D_   1024
#define H_   16
#define KD_  64
#define VD_  64
#define NQK  2048          // H*KD*2
#define NV   1024          // H*VD
#define MROWS (B_*S_)      // 8192

// ---------------------------------------------------------------------------
// Scratch (static device arrays — no runtime allocation)
// ---------------------------------------------------------------------------
__device__ float g_qk [B_*S_*NQK];        // x @ W_qk^T + b
__device__ float g_v  [B_*S_*NV];         // x @ W_v^T  + b
__device__ float g_q  [B_*H_*S_*KD_];     // [b,h,s,kd]
__device__ float g_k  [B_*H_*S_*KD_];
__device__ float g_vp [B_*H_*S_*VD_];
__device__ float g_ao [B_*S_*NV];         // attention out, [b,s, h*64+vd]
__device__ float g_psum[512];
__device__ float g_psq [512];
__device__ float g_stats[16];             // per-batch {sum, sumsq}

// ---------------------------------------------------------------------------
// TF32 helpers
// ---------------------------------------------------------------------------
__device__ __forceinline__ unsigned f2tf32(float f) {
    unsigned r;
    asm("cvt.rna.tf32.f32 %0, %1;" : "=r"(r) : "f"(f));
    return r;
}
__device__ __forceinline__ void mma_tf32(float& c0, float& c1, float& c2, float& c3,
                                         unsigned a0, unsigned a1, unsigned a2, unsigned a3,
                                         unsigned b0, unsigned b1) {
    asm volatile(
        "mma.sync.aligned.m16n8k8.row.col.f32.tf32.tf32.f32 "
        "{%0,%1,%2,%3}, {%4,%5,%6,%7}, {%8,%9}, {%0,%1,%2,%3};"
        : "+f"(c0), "+f"(c1), "+f"(c2), "+f"(c3)
        : "r"(a0), "r"(a1), "r"(a2), "r"(a3), "r"(b0), "r"(b1));
}

// FMA-pipe exp2: no MUFU. arg clamped; 2^f poly (deg 6, err ~1e-7); 2^r via
// exponent-field add using the magic-number round trick.
__device__ __forceinline__ float fexp2(float y) {
    y = fmaxf(y, -80.f);
    float tt = y + 12582912.f;                 // 1.5*2^23: round-to-nearest
    float f  = y - (tt - 12582912.f);          // f in [-0.5, 0.5]
    float p  = 1.5403530393381610e-4f;
    p = p * f + 1.3333558146428443e-3f;
    p = p * f + 9.6181291076284770e-3f;
    p = p * f + 5.5504108664821580e-2f;
    p = p * f + 2.4022650695910071e-1f;
    p = p * f + 6.9314718055994531e-1f;
    p = p * f + 1.0f;
    return __int_as_float(__float_as_int(p) + (__float_as_int(tt) << 23));
}

// ---------------------------------------------------------------------------
// TF32 tensor-core GEMM: C[M,N] = A[M,1024] @ W[N,1024]^T + bias[N]
// 128x128 CTA, 8 warps (2M x 4N), warp tile 64x32, BK=16
// ---------------------------------------------------------------------------
#define GP 20   // smem pitch in floats

__global__ __launch_bounds__(256, 2)
void tgemm_bias(const float* __restrict__ A, const float* __restrict__ W,
                const float* __restrict__ bias, float* __restrict__ C, int N)
{
    __shared__ unsigned As[128 * GP];
    __shared__ unsigned Ws[128 * GP];
    const int K = 1024;
    int tid = threadIdx.x;
    int warpId = tid >> 5, lane = tid & 31;
    int wm = warpId >> 2, wn = warpId & 3;
    int g = lane >> 2, t = lane & 3;
    int m0 = blockIdx.y * 128, n0 = blockIdx.x * 128;

    float c[4][4][4];   // [tm][tn][frag]
#pragma unroll
    for (int i = 0; i < 4; i++)
#pragma unroll
        for (int j = 0; j < 4; j++)
#pragma unroll
            for (int f = 0; f < 4; f++) c[i][j][f] = 0.f;

    for (int k0 = 0; k0 < K; k0 += 16) {
#pragma unroll
        for (int l = 0; l < 2; l++) {
            int i4 = tid + l * 256;
            int r  = i4 >> 2;
            int c4 = (i4 & 3) * 4;
            float4 a = *reinterpret_cast<const float4*>(&A[(size_t)(m0 + r) * K + k0 + c4]);
            As[r * GP + c4 + 0] = f2tf32(a.x);
            As[r * GP + c4 + 1] = f2tf32(a.y);
            As[r * GP + c4 + 2] = f2tf32(a.z);
            As[r * GP + c4 + 3] = f2tf32(a.w);
            float4 b = *reinterpret_cast<const float4*>(&W[(size_t)(n0 + r) * K + k0 + c4]);
            Ws[r * GP + c4 + 0] = f2tf32(b.x);
            Ws[r * GP + c4 + 1] = f2tf32(b.y);
            Ws[r * GP + c4 + 2] = f2tf32(b.z);
            Ws[r * GP + c4 + 3] = f2tf32(b.w);
        }
        __syncthreads();

#pragma unroll
        for (int ks = 0; ks < 16; ks += 8) {
            unsigned af[4][4], bf[4][2];
#pragma unroll
            for (int tm = 0; tm < 4; tm++) {
                int row = wm * 64 + tm * 16 + g;
                af[tm][0] = As[row * GP + ks + t];
                af[tm][1] = As[(row + 8) * GP + ks + t];
                af[tm][2] = As[row * GP + ks + 4 + t];
                af[tm][3] = As[(row + 8) * GP + ks + 4 + t];
            }
#pragma unroll
            for (int tn = 0; tn < 4; tn++) {
                int rowb = wn * 32 + tn * 8 + g;
                bf[tn][0] = Ws[rowb * GP + ks + t];
                bf[tn][1] = Ws[rowb * GP + ks + 4 + t];
            }
#pragma unroll
            for (int tm = 0; tm < 4; tm++)
#pragma unroll
                for (int tn = 0; tn < 4; tn++)
                    mma_tf32(c[tm][tn][0], c[tm][tn][1], c[tm][tn][2], c[tm][tn][3],
                             af[tm][0], af[tm][1], af[tm][2], af[tm][3],
                             bf[tn][0], bf[tn][1]);
        }
        __syncthreads();
    }

#pragma unroll
    for (int tm = 0; tm < 4; tm++) {
        int row = m0 + wm * 64 + tm * 16 + g;
#pragma unroll
        for (int tn = 0; tn < 4; tn++) {
            int col = n0 + wn * 32 + tn * 8 + 2 * t;
            float2 o0, o1;
            o0.x = c[tm][tn][0] + bias[col];
            o0.y = c[tm][tn][1] + bias[col + 1];
            o1.x = c[tm][tn][2] + bias[col];
            o1.y = c[tm][tn][3] + bias[col + 1];
            *reinterpret_cast<float2*>(&C[(size_t)row * N + col])       = o0;
            *reinterpret_cast<float2*>(&C[(size_t)(row + 8) * N + col]) = o1;
        }
    }
}

// ---------------------------------------------------------------------------
// O-projection (TF32 MMA): C = A @ W_o^T + b_o + x, + per-CTA partial LN stats
// ---------------------------------------------------------------------------
__global__ __launch_bounds__(256, 2)
void tgemm_oproj(const float* __restrict__ A, const float* __restrict__ W,
                 const float* __restrict__ bias, const float* __restrict__ x,
                 float* __restrict__ C)
{
    __shared__ unsigned As[128 * GP];
    __shared__ unsigned Ws[128 * GP];
    const int K = 1024, N = 1024;
    int tid = threadIdx.x;
    int warpId = tid >> 5, lane = tid & 31;
    int wm = warpId >> 2, wn = warpId & 3;
    int g = lane >> 2, t = lane & 3;
    int m0 = blockIdx.y * 128, n0 = blockIdx.x * 128;

    float c[4][4][4];
#pragma unroll
    for (int i = 0; i < 4; i++)
#pragma unroll
        for (int j = 0; j < 4; j++)
#pragma unroll
            for (int f = 0; f < 4; f++) c[i][j][f] = 0.f;

    for (int k0 = 0; k0 < K; k0 += 16) {
#pragma unroll
        for (int l = 0; l < 2; l++) {
            int i4 = tid + l * 256;
            int r  = i4 >> 2;
            int c4 = (i4 & 3) * 4;
            float4 a = *reinterpret_cast<const float4*>(&A[(size_t)(m0 + r) * K + k0 + c4]);
            As[r * GP + c4 + 0] = f2tf32(a.x);
            As[r * GP + c4 + 1] = f2tf32(a.y);
            As[r * GP + c4 + 2] = f2tf32(a.z);
            As[r * GP + c4 + 3] = f2tf32(a.w);
            float4 b = *reinterpret_cast<const float4*>(&W[(size_t)(n0 + r) * K + k0 + c4]);
            Ws[r * GP + c4 + 0] = f2tf32(b.x);
            Ws[r * GP + c4 + 1] = f2tf32(b.y);
            Ws[r * GP + c4 + 2] = f2tf32(b.z);
            Ws[r * GP + c4 + 3] = f2tf32(b.w);
        }
        __syncthreads();

#pragma unroll
        for (int ks = 0; ks < 16; ks += 8) {
            unsigned af[4][4], bf[4][2];
#pragma unroll
            for (int tm = 0; tm < 4; tm++) {
                int row = wm * 64 + tm * 16 + g;
                af[tm][0] = As[row * GP + ks + t];
                af[tm][1] = As[(row + 8) * GP + ks + t];
                af[tm][2] = As[row * GP + ks + 4 + t];
                af[tm][3] = As[(row + 8) * GP + ks + 4 + t];
            }
#pragma unroll
            for (int tn = 0; tn < 4; tn++) {
                int rowb = wn * 32 + tn * 8 + g;
                bf[tn][0] = Ws[rowb * GP + ks + t];
                bf[tn][1] = Ws[rowb * GP + ks + 4 + t];
            }
#pragma unroll
            for (int tm = 0; tm < 4; tm++)
#pragma unroll
                for (int tn = 0; tn < 4; tn++)
                    mma_tf32(c[tm][tn][0], c[tm][tn][1], c[tm][tn][2], c[tm][tn][3],
                             af[tm][0], af[tm][1], af[tm][2], af[tm][3],
                             bf[tn][0], bf[tn][1]);
        }
        __syncthreads();
    }

    float lsum = 0.f, lsq = 0.f;
#pragma unroll
    for (int tm = 0; tm < 4; tm++) {
        int row = m0 + wm * 64 + tm * 16 + g;
#pragma unroll
        for (int tn = 0; tn < 4; tn++) {
            int col = n0 + wn * 32 + tn * 8 + 2 * t;
            float2 x0 = *reinterpret_cast<const float2*>(&x[(size_t)row * N + col]);
            float2 x1 = *reinterpret_cast<const float2*>(&x[(size_t)(row + 8) * N + col]);
            float2 o0, o1;
            o0.x = c[tm][tn][0] + bias[col]     + x0.x;
            o0.y = c[tm][tn][1] + bias[col + 1] + x0.y;
            o1.x = c[tm][tn][2] + bias[col]     + x1.x;
            o1.y = c[tm][tn][3] + bias[col + 1] + x1.y;
            *reinterpret_cast<float2*>(&C[(size_t)row * N + col])       = o0;
            *reinterpret_cast<float2*>(&C[(size_t)(row + 8) * N + col]) = o1;
            lsum += o0.x + o0.y + o1.x + o1.y;
            lsq  += o0.x*o0.x + o0.y*o0.y + o1.x*o1.x + o1.y*o1.y;
        }
    }
#pragma unroll
    for (int off = 16; off > 0; off >>= 1) {
        lsum += __shfl_down_sync(0xffffffffu, lsum, off);
        lsq  += __shfl_down_sync(0xffffffffu, lsq,  off);
    }
    __shared__ float rs[8], rq[8];
    if (lane == 0) { rs[warpId] = lsum; rq[warpId] = lsq; }
    __syncthreads();
    if (tid == 0) {
        float s = 0.f, q = 0.f;
#pragma unroll
        for (int w = 0; w < 8; w++) { s += rs[w]; q += rq[w]; }
        int p = blockIdx.y * 8 + blockIdx.x;   // 0..511, 64 per batch
        g_psum[p] = s; g_psq[p] = q;
    }
}

// ---------------------------------------------------------------------------
// Repack: de-interleave qk/v channel layouts into [b,h,s,64] contiguous
// ---------------------------------------------------------------------------
__global__ void repack_kernel()
{
    __shared__ float sqk[2048 + 64];
    __shared__ float sv [1024 + 32];
    int bs = blockIdx.x;            // 0..8191
    int b = bs >> 10, s = bs & 1023;
    int tid = threadIdx.x;          // 256
    const float* qkrow = g_qk + (size_t)bs * NQK;
    const float* vrow  = g_v  + (size_t)bs * NV;
    for (int c = tid; c < 2048; c += 256) sqk[c + (c >> 5)] = qkrow[c];
    for (int c = tid; c < 1024; c += 256) sv [c + (c >> 5)] = vrow[c];
    __syncthreads();
    for (int idx = tid; idx < 1024; idx += 256) {
        int h = idx >> 6, kd = idx & 63;
        int cq = kd * 32 + h;
        int ck = cq + 16;
        int cv = kd * 16 + h;
        size_t o = ((size_t)(b * H_ + h) * S_ + s) * 64 + kd;
        g_q [o] = sqk[cq + (cq >> 5)];
        g_k [o] = sqk[ck + (ck >> 5)];
        g_vp[o] = sv [cv + (cv >> 5)];
    }
}

// ---------------------------------------------------------------------------
// TF32 tensor-core flash attention.
// CTA = (b, h, 128 q-rows); 8 warps, warp owns 16 rows; j-tiles of 64.
// Q frags in registers; S=QK^T and O+=PV via m16n8k8; exp2 on FMA pipe.
// Smem pitch 68 (mod 32 = 4) -> Q/K/P fragment accesses conflict-free.
// ---------------------------------------------------------------------------
#define PA 68
#define AT_SMEM_BYTES (256 * PA * 4)   // Q/P[128] + K[64] + V[64] rows

__global__ __launch_bounds__(256, 2)
void attn_tc_kernel()
{
    extern __shared__ unsigned smu[];
    unsigned* Qs = smu;              // [128][PA]; reused as Ps after Q-frag load
    unsigned* Ks = smu + 128 * PA;   // [64][PA]   K[j][kd]
    unsigned* Vs = Ks + 64 * PA;     // [64][PA]   V[j][vd]

    int tid  = threadIdx.x;
    int warp = tid >> 5, lane = tid & 31;
    int g = lane >> 2, t = lane & 3;
    int i0 = blockIdx.x * 128;
    int h  = blockIdx.y, b = blockIdx.z;
    int bh = b * H_ + h;
    const float* Qb = g_q  + ((size_t)bh * S_ + i0) * KD_;
    const float* Kb = g_k  + (size_t)bh * S_ * KD_;
    const float* Vb = g_vp + (size_t)bh * S_ * VD_;
    const float QSCL = 0.125f * 1.4426950408889634f;  // 1/sqrt(64) * log2(e)

    // stage Q (scaled into log2 domain), convert to tf32
    for (int idx = tid; idx < 128 * 16; idx += 256) {
        int r = idx >> 4, c4 = (idx & 15) * 4;
        float4 q = *reinterpret_cast<const float4*>(&Qb[(size_t)r * 64 + c4]);
        Qs[r * PA + c4 + 0] = f2tf32(q.x * QSCL);
        Qs[r * PA + c4 + 1] = f2tf32(q.y * QSCL);
        Qs[r * PA + c4 + 2] = f2tf32(q.z * QSCL);
        Qs[r * PA + c4 + 3] = f2tf32(q.w * QSCL);
    }
    __syncthreads();

    // A-fragments of Q for this warp's 16 rows, all 8 k-steps -> registers
    int wr = warp * 16;
    unsigned qf[8][4];
#pragma unroll
    for (int k = 0; k < 8; k++) {
        qf[k][0] = Qs[(wr + g)     * PA + k * 8 + t];
        qf[k][1] = Qs[(wr + g + 8) * PA + k * 8 + t];
        qf[k][2] = Qs[(wr + g)     * PA + k * 8 + 4 + t];
        qf[k][3] = Qs[(wr + g + 8) * PA + k * 8 + 4 + t];
    }
    __syncthreads();            // Qs region now free -> becomes Ps
    unsigned* Ps = Qs;

    float accO[8][4];
#pragma unroll
    for (int n = 0; n < 8; n++)
#pragma unroll
        for (int f = 0; f < 4; f++) accO[n][f] = 0.f;
    float m0 = -1e30f, m1 = -1e30f, l0 = 0.f, l1 = 0.f;

    for (int j0 = 0; j0 < S_; j0 += 64) {
        // load K/V tiles (tf32)
        for (int idx = tid; idx < 64 * 16; idx += 256) {
            int r = idx >> 4, c4 = (idx & 15) * 4;
            float4 kv = *reinterpret_cast<const float4*>(&Kb[(size_t)(j0 + r) * 64 + c4]);
            Ks[r * PA + c4 + 0] = f2tf32(kv.x);
            Ks[r * PA + c4 + 1] = f2tf32(kv.y);
            Ks[r * PA + c4 + 2] = f2tf32(kv.z);
            Ks[r * PA + c4 + 3] = f2tf32(kv.w);
            float4 vv = *reinterpret_cast<const float4*>(&Vb[(size_t)(j0 + r) * 64 + c4]);
            Vs[r * PA + c4 + 0] = f2tf32(vv.x);
            Vs[r * PA + c4 + 1] = f2tf32(vv.y);
            Vs[r * PA + c4 + 2] = f2tf32(vv.z);
            Vs[r * PA + c4 + 3] = f2tf32(vv.w);
        }
        __syncthreads();

        // S = Q K^T  (warp: 16 x 64)
        float sacc[8][4];
#pragma unroll
        for (int n = 0; n < 8; n++)
#pragma unroll
            for (int f = 0; f < 4; f++) sacc[n][f] = 0.f;
#pragma unroll
        for (int k = 0; k < 8; k++) {
#pragma unroll
            for (int n = 0; n < 8; n++) {
                unsigned b0 = Ks[(n * 8 + g) * PA + k * 8 + t];
                unsigned b1 = Ks[(n * 8 + g) * PA + k * 8 + 4 + t];
                mma_tf32(sacc[n][0], sacc[n][1], sacc[n][2], sacc[n][3],
                         qf[k][0], qf[k][1], qf[k][2], qf[k][3], b0, b1);
            }
        }

        // online softmax (rows wr+g and wr+g+8), exp2 on FMA pipe
        float tm0 = -1e30f, tm1 = -1e30f;
#pragma unroll
        for (int n = 0; n < 8; n++) {
            tm0 = fmaxf(tm0, fmaxf(sacc[n][0], sacc[n][1]));
            tm1 = fmaxf(tm1, fmaxf(sacc[n][2], sacc[n][3]));
        }
        tm0 = fmaxf(tm0, __shfl_xor_sync(0xffffffffu, tm0, 1));
        tm0 = fmaxf(tm0, __shfl_xor_sync(0xffffffffu, tm0, 2));
        tm1 = fmaxf(tm1, __shfl_xor_sync(0xffffffffu, tm1, 1));
        tm1 = fmaxf(tm1, __shfl_xor_sync(0xffffffffu, tm1, 2));
        float mn0 = fmaxf(m0, tm0), mn1 = fmaxf(m1, tm1);
        float sc0 = fexp2(m0 - mn0), sc1 = fexp2(m1 - mn1);
        float ps0 = 0.f, ps1 = 0.f;
#pragma unroll
        for (int n = 0; n < 8; n++) {
            float p0 = fexp2(sacc[n][0] - mn0);
            float p1 = fexp2(sacc[n][1] - mn0);
            float p2 = fexp2(sacc[n][2] - mn1);
            float p3 = fexp2(sacc[n][3] - mn1);
            ps0 += p0 + p1; ps1 += p2 + p3;
            Ps[(wr + g)     * PA + n * 8 + 2 * t]     = f2tf32(p0);
            Ps[(wr + g)     * PA + n * 8 + 2 * t + 1] = f2tf32(p1);
            Ps[(wr + g + 8) * PA + n * 8 + 2 * t]     = f2tf32(p2);
            Ps[(wr + g + 8) * PA + n * 8 + 2 * t + 1] = f2tf32(p3);
            accO[n][0] *= sc0; accO[n][1] *= sc0;
            accO[n][2] *= sc1; accO[n][3] *= sc1;
        }
        ps0 += __shfl_xor_sync(0xffffffffu, ps0, 1);
        ps0 += __shfl_xor_sync(0xffffffffu, ps0, 2);
        ps1 += __shfl_xor_sync(0xffffffffu, ps1, 1);
        ps1 += __shfl_xor_sync(0xffffffffu, ps1, 2);
        l0 = l0 * sc0 + ps0;
        l1 = l1 * sc1 + ps1;
        m0 = mn0; m1 = mn1;
        __syncwarp();   // P staging is warp-private

        // O += P V   (A-frags from Ps, B-frags from Vs with (k,n) index swap)
#pragma unroll
        for (int k = 0; k < 8; k++) {
            unsigned a0 = Ps[(wr + g)     * PA + k * 8 + t];
            unsigned a1 = Ps[(wr + g + 8) * PA + k * 8 + t];
            unsigned a2 = Ps[(wr + g)     * PA + k * 8 + 4 + t];
            unsigned a3 = Ps[(wr + g + 8) * PA + k * 8 + 4 + t];
#pragma unroll
            for (int n = 0; n < 8; n++) {
                unsigned b0 = Vs[(k * 8 + t)     * PA + n * 8 + g];
                unsigned b1 = Vs[(k * 8 + t + 4) * PA + n * 8 + g];
                mma_tf32(accO[n][0], accO[n][1], accO[n][2], accO[n][3],
                         a0, a1, a2, a3, b0, b1);
            }
        }
        __syncthreads();  // before next tile overwrites Ks/Vs
    }

    // epilogue: normalize, write [b, s, h*64+vd]
    float inv0 = 1.f / l0, inv1 = 1.f / l1;
    int row0 = i0 + wr + g, row1 = row0 + 8;
#pragma unroll
    for (int n = 0; n < 8; n++) {
        int col = h * 64 + n * 8 + 2 * t;
        float2 o0, o1;
        o0.x = accO[n][0] * inv0; o0.y = accO[n][1] * inv0;
        o1.x = accO[n][2] * inv1; o1.y = accO[n][3] * inv1;
        *reinterpret_cast<float2*>(&g_ao[(size_t)(b * S_ + row0) * NV + col]) = o0;
        *reinterpret_cast<float2*>(&g_ao[(size_t)(b * S_ + row1) * NV + col]) = o1;
    }
}

// ---------------------------------------------------------------------------
// LN stats reduce + finalize
// ---------------------------------------------------------------------------
__global__ void stats_reduce()
{
    int w = threadIdx.x >> 5, lane = threadIdx.x & 31;
    float s = g_psum[w * 64 + lane] + g_psum[w * 64 + 32 + lane];
    float q = g_psq [w * 64 + lane] + g_psq [w * 64 + 32 + lane];
#pragma unroll
    for (int off = 16; off > 0; off >>= 1) {
        s += __shfl_down_sync(0xffffffffu, s, off);
        q += __shfl_down_sync(0xffffffffu, q, off);
    }
    if (lane == 0) { g_stats[2 * w] = s; g_stats[2 * w + 1] = q; }
}

__global__ void ln_finalize(float* __restrict__ y,
                            const float* __restrict__ lnw,
                            const float* __restrict__ lnb)
{
    int idx = blockIdx.x * 256 + threadIdx.x;
    int b   = idx >> 18;
    int sd4 = idx & ((1 << 18) - 1);
    const float invn = 1.0f / 1048576.0f;
    float mean = g_stats[2 * b] * invn;
    float var  = g_stats[2 * b + 1] * invn - mean * mean;
    float inv  = rsqrtf(var + 1e-5f);
    float4 v  = reinterpret_cast<float4*>(y)[idx];
    float4 w  = reinterpret_cast<const float4*>(lnw)[sd4];
    float4 bb = reinterpret_cast<const float4*>(lnb)[sd4];
    v.x = (v.x - mean) * inv * w.x + bb.x;
    v.y = (v.y - mean) * inv * w.y + bb.y;
    v.z = (v.z - mean) * inv * w.z + bb.z;
    v.w = (v.w - mean) * inv * w.w + bb.w;
    reinterpret_cast<float4*>(y)[idx] = v;
}

// ---------------------------------------------------------------------------
// kernel_launch
// ---------------------------------------------------------------------------
extern "C" void kernel_launch(void* const* d_in, const int* in_sizes, int n_in,
                              void* d_out, int out_size)
{
    const float* x    = (const float*)d_in[0];
    const float* W_qk = (const float*)d_in[1];
    const float* b_qk = (const float*)d_in[2];
    const float* W_v  = (const float*)d_in[3];
    const float* b_v  = (const float*)d_in[4];
    const float* W_o  = (const float*)d_in[5];
    const float* b_o  = (const float*)d_in[6];
    const float* ln_w = (const float*)d_in[7];
    const float* ln_b = (const float*)d_in[8];
    float* out = (float*)d_out;

    void *p_qk, *p_v, *p_ao;
    cudaGetSymbolAddress(&p_qk, g_qk);
    cudaGetSymbolAddress(&p_v,  g_v);
    cudaGetSymbolAddress(&p_ao, g_ao);

    cudaFuncSetAttribute(attn_tc_kernel, cudaFuncAttributeMaxDynamicSharedMemorySize,
                         AT_SMEM_BYTES);

    // 1) qk = x @ W_qk^T + b_qk   (8192 x 2048) — TF32 MMA
    tgemm_bias<<<dim3(NQK / 128, MROWS / 128), 256>>>(x, W_qk, b_qk, (float*)p_qk, NQK);
    // 2) v  = x @ W_v^T + b_v     (8192 x 1024) — TF32 MMA
    tgemm_bias<<<dim3(NV / 128, MROWS / 128), 256>>>(x, W_v, b_v, (float*)p_v, NV);
    // 3) repack into [b,h,s,64]
    repack_kernel<<<MROWS, 256>>>();
    // 4) flash attention — TF32 MMA + FMA-pipe exp2
    attn_tc_kernel<<<dim3(S_ / 128, H_, B_), 256, AT_SMEM_BYTES>>>();
    // 5) O-proj (TF32 MMA) + bias + residual + partial LN stats
    tgemm_oproj<<<dim3(NV / 128, MROWS / 128), 256>>>((const float*)p_ao, W_o, b_o, x, out);
    // 6) reduce stats per batch
    stats_reduce<<<1, 256>>>();
    // 7) LayerNorm finalize
    ln_finalize<<<(B_ * S_ * D_ / 4) / 256, 256>>>(out, ln_w, ln_b);
}

// round 7
// speedup vs baseline: 1.1554x; 1.1554x over previous
#include <cuda_runtime.h>
#include <cuda_pipeline.h>
#include <math.h>

// Problem constants
#define B_   8
#define S_   1024
#define D_   1024
#define H_   16
#define KD_  64
#define VD_  64
#define NQK  2048          // H*KD*2
#define NV   1024          // H*VD
#define MROWS (B_*S_)      // 8192

// ---------------------------------------------------------------------------
// Scratch (static device arrays — no runtime allocation)
// ---------------------------------------------------------------------------
__device__ float g_qk [B_*S_*NQK];        // x @ W_qk^T + b
__device__ float g_v  [B_*S_*NV];         // x @ W_v^T  + b
__device__ float g_q  [B_*H_*S_*KD_];     // [b,h,s,kd]
__device__ float g_k  [B_*H_*S_*KD_];     // (tf32-rounded)
__device__ float g_vp [B_*H_*S_*VD_];     // (tf32-rounded)
__device__ float g_ao [B_*S_*NV];         // attention out (tf32-rounded)
__device__ float g_xr [B_*S_*D_];         // tf32-rounded x
__device__ float g_wqk[NQK*D_];           // tf32-rounded W_qk
__device__ float g_wv [NV*D_];            // tf32-rounded W_v
__device__ float g_wo [D_*NV];            // tf32-rounded W_o
__device__ float g_psum[512];
__device__ float g_psq [512];
__device__ float g_stats[16];             // per-batch {sum, sumsq}

// ---------------------------------------------------------------------------
// TF32 helpers
// ---------------------------------------------------------------------------
__device__ __forceinline__ unsigned f2tf32(float f) {
    unsigned r;
    asm("cvt.rna.tf32.f32 %0, %1;" : "=r"(r) : "f"(f));
    return r;
}
__device__ __forceinline__ float rtf(float f) { return __uint_as_float(f2tf32(f)); }

__device__ __forceinline__ void mma_tf32(float& c0, float& c1, float& c2, float& c3,
                                         unsigned a0, unsigned a1, unsigned a2, unsigned a3,
                                         unsigned b0, unsigned b1) {
    asm volatile(
        "mma.sync.aligned.m16n8k8.row.col.f32.tf32.tf32.f32 "
        "{%0,%1,%2,%3}, {%4,%5,%6,%7}, {%8,%9}, {%0,%1,%2,%3};"
        : "+f"(c0), "+f"(c1), "+f"(c2), "+f"(c3)
        : "r"(a0), "r"(a1), "r"(a2), "r"(a3), "r"(b0), "r"(b1));
}

// FMA-pipe exp2 (no MUFU): deg-6 poly + exponent-field add
__device__ __forceinline__ float fexp2(float y) {
    y = fmaxf(y, -80.f);
    float tt = y + 12582912.f;                 // 1.5*2^23: round-to-nearest
    float f  = y - (tt - 12582912.f);          // f in [-0.5, 0.5]
    float p  = 1.5403530393381610e-4f;
    p = p * f + 1.3333558146428443e-3f;
    p = p * f + 9.6181291076284770e-3f;
    p = p * f + 5.5504108664821580e-2f;
    p = p * f + 2.4022650695910071e-1f;
    p = p * f + 6.9314718055994531e-1f;
    p = p * f + 1.0f;
    return __int_as_float(__float_as_int(p) + (__float_as_int(tt) << 23));
}

// ---------------------------------------------------------------------------
// tf32 pre-rounding pass (makes raw-byte cp.async == exact rna rounding)
// ---------------------------------------------------------------------------
__global__ void round_tf32_kernel(float* __restrict__ dst, const float* __restrict__ src)
{
    int i = blockIdx.x * 256 + threadIdx.x;
    float4 v = reinterpret_cast<const float4*>(src)[i];
    v.x = rtf(v.x); v.y = rtf(v.y); v.z = rtf(v.z); v.w = rtf(v.w);
    reinterpret_cast<float4*>(dst)[i] = v;
}

// ---------------------------------------------------------------------------
// TF32 tensor-core GEMM, cp.async 2-stage pipeline.
// C[M,N] = A[M,1024] @ W[N,1024]^T + bias[N]; A/W pre-rounded to tf32.
// 128x128 CTA, 8 warps (2M x 4N), BK=16, pitch 20 (conflict-free frags)
// ---------------------------------------------------------------------------
#define GP 20   // smem pitch in 32-bit words

__global__ __launch_bounds__(256, 2)
void tgemm_bias(const float* __restrict__ A, const float* __restrict__ W,
                const float* __restrict__ bias, float* __restrict__ C, int N)
{
    __shared__ unsigned As[2][128 * GP];
    __shared__ unsigned Ws[2][128 * GP];
    const int K = 1024;
    int tid = threadIdx.x;
    int warpId = tid >> 5, lane = tid & 31;
    int wm = warpId >> 2, wn = warpId & 3;
    int g = lane >> 2, t = lane & 3;
    int m0 = blockIdx.y * 128, n0 = blockIdx.x * 128;
    int r_ld = tid >> 2, c4_ld = (tid & 3) * 4;

    float c[4][4][4];
#pragma unroll
    for (int i = 0; i < 4; i++)
#pragma unroll
        for (int j = 0; j < 4; j++)
#pragma unroll
            for (int f = 0; f < 4; f++) c[i][j][f] = 0.f;

    auto load_stage = [&](int st, int k0) {
#pragma unroll
        for (int l = 0; l < 2; l++) {
            int r = r_ld + l * 64;
            __pipeline_memcpy_async(&As[st][r * GP + c4_ld],
                                    &A[(size_t)(m0 + r) * K + k0 + c4_ld], 16);
            __pipeline_memcpy_async(&Ws[st][r * GP + c4_ld],
                                    &W[(size_t)(n0 + r) * K + k0 + c4_ld], 16);
        }
    };

    load_stage(0, 0);
    __pipeline_commit();

    int cur = 0;
    for (int k0 = 0; k0 < K; k0 += 16) {
        if (k0 + 16 < K) {
            load_stage(cur ^ 1, k0 + 16);
            __pipeline_commit();
            __pipeline_wait_prior(1);
        } else {
            __pipeline_wait_prior(0);
        }
        __syncthreads();

#pragma unroll
        for (int ks = 0; ks < 16; ks += 8) {
            unsigned af[4][4], bf[4][2];
#pragma unroll
            for (int tm = 0; tm < 4; tm++) {
                int row = wm * 64 + tm * 16 + g;
                af[tm][0] = As[cur][row * GP + ks + t];
                af[tm][1] = As[cur][(row + 8) * GP + ks + t];
                af[tm][2] = As[cur][row * GP + ks + 4 + t];
                af[tm][3] = As[cur][(row + 8) * GP + ks + 4 + t];
            }
#pragma unroll
            for (int tn = 0; tn < 4; tn++) {
                int rowb = wn * 32 + tn * 8 + g;
                bf[tn][0] = Ws[cur][rowb * GP + ks + t];
                bf[tn][1] = Ws[cur][rowb * GP + ks + 4 + t];
            }
#pragma unroll
            for (int tm = 0; tm < 4; tm++)
#pragma unroll
                for (int tn = 0; tn < 4; tn++)
                    mma_tf32(c[tm][tn][0], c[tm][tn][1], c[tm][tn][2], c[tm][tn][3],
                             af[tm][0], af[tm][1], af[tm][2], af[tm][3],
                             bf[tn][0], bf[tn][1]);
        }
        __syncthreads();
        cur ^= 1;
    }

#pragma unroll
    for (int tm = 0; tm < 4; tm++) {
        int row = m0 + wm * 64 + tm * 16 + g;
#pragma unroll
        for (int tn = 0; tn < 4; tn++) {
            int col = n0 + wn * 32 + tn * 8 + 2 * t;
            float2 o0, o1;
            o0.x = c[tm][tn][0] + bias[col];
            o0.y = c[tm][tn][1] + bias[col + 1];
            o1.x = c[tm][tn][2] + bias[col];
            o1.y = c[tm][tn][3] + bias[col + 1];
            *reinterpret_cast<float2*>(&C[(size_t)row * N + col])       = o0;
            *reinterpret_cast<float2*>(&C[(size_t)(row + 8) * N + col]) = o1;
        }
    }
}

// ---------------------------------------------------------------------------
// O-projection (pipelined TF32 MMA): C = A @ W_o^T + b_o + x, + LN partials
// ---------------------------------------------------------------------------
__global__ __launch_bounds__(256, 2)
void tgemm_oproj(const float* __restrict__ A, const float* __restrict__ W,
                 const float* __restrict__ bias, const float* __restrict__ x,
                 float* __restrict__ C)
{
    __shared__ unsigned As[2][128 * GP];
    __shared__ unsigned Ws[2][128 * GP];
    const int K = 1024, N = 1024;
    int tid = threadIdx.x;
    int warpId = tid >> 5, lane = tid & 31;
    int wm = warpId >> 2, wn = warpId & 3;
    int g = lane >> 2, t = lane & 3;
    int m0 = blockIdx.y * 128, n0 = blockIdx.x * 128;
    int r_ld = tid >> 2, c4_ld = (tid & 3) * 4;

    float c[4][4][4];
#pragma unroll
    for (int i = 0; i < 4; i++)
#pragma unroll
        for (int j = 0; j < 4; j++)
#pragma unroll
            for (int f = 0; f < 4; f++) c[i][j][f] = 0.f;

    auto load_stage = [&](int st, int k0) {
#pragma unroll
        for (int l = 0; l < 2; l++) {
            int r = r_ld + l * 64;
            __pipeline_memcpy_async(&As[st][r * GP + c4_ld],
                                    &A[(size_t)(m0 + r) * K + k0 + c4_ld], 16);
            __pipeline_memcpy_async(&Ws[st][r * GP + c4_ld],
                                    &W[(size_t)(n0 + r) * K + k0 + c4_ld], 16);
        }
    };

    load_stage(0, 0);
    __pipeline_commit();

    int cur = 0;
    for (int k0 = 0; k0 < K; k0 += 16) {
        if (k0 + 16 < K) {
            load_stage(cur ^ 1, k0 + 16);
            __pipeline_commit();
            __pipeline_wait_prior(1);
        } else {
            __pipeline_wait_prior(0);
        }
        __syncthreads();

#pragma unroll
        for (int ks = 0; ks < 16; ks += 8) {
            unsigned af[4][4], bf[4][2];
#pragma unroll
            for (int tm = 0; tm < 4; tm++) {
                int row = wm * 64 + tm * 16 + g;
                af[tm][0] = As[cur][row * GP + ks + t];
                af[tm][1] = As[cur][(row + 8) * GP + ks + t];
                af[tm][2] = As[cur][row * GP + ks + 4 + t];
                af[tm][3] = As[cur][(row + 8) * GP + ks + 4 + t];
            }
#pragma unroll
            for (int tn = 0; tn < 4; tn++) {
                int rowb = wn * 32 + tn * 8 + g;
                bf[tn][0] = Ws[cur][rowb * GP + ks + t];
                bf[tn][1] = Ws[cur][rowb * GP + ks + 4 + t];
            }
#pragma unroll
            for (int tm = 0; tm < 4; tm++)
#pragma unroll
                for (int tn = 0; tn < 4; tn++)
                    mma_tf32(c[tm][tn][0], c[tm][tn][1], c[tm][tn][2], c[tm][tn][3],
                             af[tm][0], af[tm][1], af[tm][2], af[tm][3],
                             bf[tn][0], bf[tn][1]);
        }
        __syncthreads();
        cur ^= 1;
    }

    float lsum = 0.f, lsq = 0.f;
#pragma unroll
    for (int tm = 0; tm < 4; tm++) {
        int row = m0 + wm * 64 + tm * 16 + g;
#pragma unroll
        for (int tn = 0; tn < 4; tn++) {
            int col = n0 + wn * 32 + tn * 8 + 2 * t;
            float2 x0 = *reinterpret_cast<const float2*>(&x[(size_t)row * N + col]);
            float2 x1 = *reinterpret_cast<const float2*>(&x[(size_t)(row + 8) * N + col]);
            float2 o0, o1;
            o0.x = c[tm][tn][0] + bias[col]     + x0.x;
            o0.y = c[tm][tn][1] + bias[col + 1] + x0.y;
            o1.x = c[tm][tn][2] + bias[col]     + x1.x;
            o1.y = c[tm][tn][3] + bias[col + 1] + x1.y;
            *reinterpret_cast<float2*>(&C[(size_t)row * N + col])       = o0;
            *reinterpret_cast<float2*>(&C[(size_t)(row + 8) * N + col]) = o1;
            lsum += o0.x + o0.y + o1.x + o1.y;
            lsq  += o0.x*o0.x + o0.y*o0.y + o1.x*o1.x + o1.y*o1.y;
        }
    }
#pragma unroll
    for (int off = 16; off > 0; off >>= 1) {
        lsum += __shfl_down_sync(0xffffffffu, lsum, off);
        lsq  += __shfl_down_sync(0xffffffffu, lsq,  off);
    }
    __shared__ float rs[8], rq[8];
    if (lane == 0) { rs[warpId] = lsum; rq[warpId] = lsq; }
    __syncthreads();
    if (tid == 0) {
        float s = 0.f, q = 0.f;
#pragma unroll
        for (int w = 0; w < 8; w++) { s += rs[w]; q += rq[w]; }
        int p = blockIdx.y * 8 + blockIdx.x;   // 0..511, 64 per batch
        g_psum[p] = s; g_psq[p] = q;
    }
}

// ---------------------------------------------------------------------------
// Repack: de-interleave qk/v into [b,h,s,64]; K/V tf32-rounded so the
// attention kernel can raw-copy them with cp.async.
// ---------------------------------------------------------------------------
__global__ void repack_kernel()
{
    __shared__ float sqk[2048 + 64];
    __shared__ float sv [1024 + 32];
    int bs = blockIdx.x;            // 0..8191
    int b = bs >> 10, s = bs & 1023;
    int tid = threadIdx.x;          // 256
    const float* qkrow = g_qk + (size_t)bs * NQK;
    const float* vrow  = g_v  + (size_t)bs * NV;
    for (int c = tid; c < 2048; c += 256) sqk[c + (c >> 5)] = qkrow[c];
    for (int c = tid; c < 1024; c += 256) sv [c + (c >> 5)] = vrow[c];
    __syncthreads();
    for (int idx = tid; idx < 1024; idx += 256) {
        int h = idx >> 6, kd = idx & 63;
        int cq = kd * 32 + h;
        int ck = cq + 16;
        int cv = kd * 16 + h;
        size_t o = ((size_t)(b * H_ + h) * S_ + s) * 64 + kd;
        g_q [o] = sqk[cq + (cq >> 5)];            // rounded at attn staging (scaled)
        g_k [o] = rtf(sqk[ck + (ck >> 5)]);
        g_vp[o] = rtf(sv [cv + (cv >> 5)]);
    }
}

// ---------------------------------------------------------------------------
// TF32 tensor-core flash attention, cp.async 2-stage K/V pipeline.
// CTA = (b, h, 128 q-rows); 8 warps, warp owns 16 rows; j-tiles of 64.
// ---------------------------------------------------------------------------
#define PA 68
#define KV_W (64 * PA)
#define AT_SMEM_BYTES ((128 * PA + 4 * KV_W) * 4)   // Q/P + 2xK + 2xV

__global__ __launch_bounds__(256, 2)
void attn_tc_kernel()
{
    extern __shared__ unsigned smu[];
    unsigned* Qs = smu;                       // [128][PA]; becomes Ps
    unsigned* Ks = smu + 128 * PA;            // [2][64][PA]
    unsigned* Vs = smu + 128 * PA + 2 * KV_W; // [2][64][PA]

    int tid  = threadIdx.x;
    int warp = tid >> 5, lane = tid & 31;
    int g = lane >> 2, t = lane & 3;
    int i0 = blockIdx.x * 128;
    int h  = blockIdx.y, b = blockIdx.z;
    int bh = b * H_ + h;
    const float* Qb = g_q  + ((size_t)bh * S_ + i0) * KD_;
    const float* Kb = g_k  + (size_t)bh * S_ * KD_;
    const float* Vb = g_vp + (size_t)bh * S_ * VD_;
    const float QSCL = 0.125f * 1.4426950408889634f;  // 1/sqrt(64) * log2(e)

    // full-tile cp.async stage: 64 rows x 16 float4-chunks = 1024 chunks/array
    auto load_kv = [&](int st, int j0) {
#pragma unroll
        for (int l = 0; l < 4; l++) {
            int idx = tid + l * 256;            // 0..1023
            int r   = idx >> 4;                 // 0..63
            int c4  = (idx & 15) * 4;           // 0..60
            __pipeline_memcpy_async(&Ks[st * KV_W + r * PA + c4],
                                    &Kb[(size_t)(j0 + r) * 64 + c4], 16);
            __pipeline_memcpy_async(&Vs[st * KV_W + r * PA + c4],
                                    &Vb[(size_t)(j0 + r) * 64 + c4], 16);
        }
    };

    // prefetch first K/V tile, then stage Q while it flies
    load_kv(0, 0);
    __pipeline_commit();

    for (int idx = tid; idx < 128 * 16; idx += 256) {
        int r = idx >> 4, c4 = (idx & 15) * 4;
        float4 q = *reinterpret_cast<const float4*>(&Qb[(size_t)r * 64 + c4]);
        Qs[r * PA + c4 + 0] = f2tf32(q.x * QSCL);
        Qs[r * PA + c4 + 1] = f2tf32(q.y * QSCL);
        Qs[r * PA + c4 + 2] = f2tf32(q.z * QSCL);
        Qs[r * PA + c4 + 3] = f2tf32(q.w * QSCL);
    }
    __syncthreads();

    int wr = warp * 16;
    unsigned qf[8][4];
#pragma unroll
    for (int k = 0; k < 8; k++) {
        qf[k][0] = Qs[(wr + g)     * PA + k * 8 + t];
        qf[k][1] = Qs[(wr + g + 8) * PA + k * 8 + t];
        qf[k][2] = Qs[(wr + g)     * PA + k * 8 + 4 + t];
        qf[k][3] = Qs[(wr + g + 8) * PA + k * 8 + 4 + t];
    }
    __syncthreads();            // Qs region now free -> becomes Ps
    unsigned* Ps = Qs;

    float accO[8][4];
#pragma unroll
    for (int n = 0; n < 8; n++)
#pragma unroll
        for (int f = 0; f < 4; f++) accO[n][f] = 0.f;
    float m0 = -1e30f, m1 = -1e30f, l0 = 0.f, l1 = 0.f;

    int cur = 0;
    for (int j0 = 0; j0 < S_; j0 += 64) {
        if (j0 + 64 < S_) {
            load_kv(cur ^ 1, j0 + 64);
            __pipeline_commit();
            __pipeline_wait_prior(1);
        } else {
            __pipeline_wait_prior(0);
        }
        __syncthreads();
        const unsigned* Kc = Ks + cur * KV_W;
        const unsigned* Vc = Vs + cur * KV_W;

        // S = Q K^T  (warp: 16 x 64)
        float sacc[8][4];
#pragma unroll
        for (int n = 0; n < 8; n++)
#pragma unroll
            for (int f = 0; f < 4; f++) sacc[n][f] = 0.f;
#pragma unroll
        for (int k = 0; k < 8; k++) {
#pragma unroll
            for (int n = 0; n < 8; n++) {
                unsigned b0 = Kc[(n * 8 + g) * PA + k * 8 + t];
                unsigned b1 = Kc[(n * 8 + g) * PA + k * 8 + 4 + t];
                mma_tf32(sacc[n][0], sacc[n][1], sacc[n][2], sacc[n][3],
                         qf[k][0], qf[k][1], qf[k][2], qf[k][3], b0, b1);
            }
        }

        // online softmax (rows wr+g, wr+g+8), exp2 on FMA pipe
        float tm0 = -1e30f, tm1 = -1e30f;
#pragma unroll
        for (int n = 0; n < 8; n++) {
            tm0 = fmaxf(tm0, fmaxf(sacc[n][0], sacc[n][1]));
            tm1 = fmaxf(tm1, fmaxf(sacc[n][2], sacc[n][3]));
        }
        tm0 = fmaxf(tm0, __shfl_xor_sync(0xffffffffu, tm0, 1));
        tm0 = fmaxf(tm0, __shfl_xor_sync(0xffffffffu, tm0, 2));
        tm1 = fmaxf(tm1, __shfl_xor_sync(0xffffffffu, tm1, 1));
        tm1 = fmaxf(tm1, __shfl_xor_sync(0xffffffffu, tm1, 2));
        float mn0 = fmaxf(m0, tm0), mn1 = fmaxf(m1, tm1);
        float sc0 = fexp2(m0 - mn0), sc1 = fexp2(m1 - mn1);
        float ps0 = 0.f, ps1 = 0.f;
#pragma unroll
        for (int n = 0; n < 8; n++) {
            float p0 = fexp2(sacc[n][0] - mn0);
            float p1 = fexp2(sacc[n][1] - mn0);
            float p2 = fexp2(sacc[n][2] - mn1);
            float p3 = fexp2(sacc[n][3] - mn1);
            ps0 += p0 + p1; ps1 += p2 + p3;
            Ps[(wr + g)     * PA + n * 8 + 2 * t]     = f2tf32(p0);
            Ps[(wr + g)     * PA + n * 8 + 2 * t + 1] = f2tf32(p1);
            Ps[(wr + g + 8) * PA + n * 8 + 2 * t]     = f2tf32(p2);
            Ps[(wr + g + 8) * PA + n * 8 + 2 * t + 1] = f2tf32(p3);
            accO[n][0] *= sc0; accO[n][1] *= sc0;
            accO[n][2] *= sc1; accO[n][3] *= sc1;
        }
        ps0 += __shfl_xor_sync(0xffffffffu, ps0, 1);
        ps0 += __shfl_xor_sync(0xffffffffu, ps0, 2);
        ps1 += __shfl_xor_sync(0xffffffffu, ps1, 1);
        ps1 += __shfl_xor_sync(0xffffffffu, ps1, 2);
        l0 = l0 * sc0 + ps0;
        l1 = l1 * sc1 + ps1;
        m0 = mn0; m1 = mn1;
        __syncwarp();   // P staging is warp-private

        // O += P V
#pragma unroll
        for (int k = 0; k < 8; k++) {
            unsigned a0 = Ps[(wr + g)     * PA + k * 8 + t];
            unsigned a1 = Ps[(wr + g + 8) * PA + k * 8 + t];
            unsigned a2 = Ps[(wr + g)     * PA + k * 8 + 4 + t];
            unsigned a3 = Ps[(wr + g + 8) * PA + k * 8 + 4 + t];
#pragma unroll
            for (int n = 0; n < 8; n++) {
                unsigned b0 = Vc[(k * 8 + t)     * PA + n * 8 + g];
                unsigned b1 = Vc[(k * 8 + t + 4) * PA + n * 8 + g];
                mma_tf32(accO[n][0], accO[n][1], accO[n][2], accO[n][3],
                         a0, a1, a2, a3, b0, b1);
            }
        }
        __syncthreads();  // stage cur may be overwritten next iteration
        cur ^= 1;
    }

    // epilogue: normalize, round to tf32 (oproj raw-copies it), write
    float inv0 = 1.f / l0, inv1 = 1.f / l1;
    int row0 = i0 + wr + g, row1 = row0 + 8;
#pragma unroll
    for (int n = 0; n < 8; n++) {
        int col = h * 64 + n * 8 + 2 * t;
        float2 o0, o1;
        o0.x = rtf(accO[n][0] * inv0); o0.y = rtf(accO[n][1] * inv0);
        o1.x = rtf(accO[n][2] * inv1); o1.y = rtf(accO[n][3] * inv1);
        *reinterpret_cast<float2*>(&g_ao[(size_t)(b * S_ + row0) * NV + col]) = o0;
        *reinterpret_cast<float2*>(&g_ao[(size_t)(b * S_ + row1) * NV + col]) = o1;
    }
}

// ---------------------------------------------------------------------------
// LN stats reduce + finalize
// ---------------------------------------------------------------------------
__global__ void stats_reduce()
{
    int w = threadIdx.x >> 5, lane = threadIdx.x & 31;
    float s = g_psum[w * 64 + lane] + g_psum[w * 64 + 32 + lane];
    float q = g_psq [w * 64 + lane] + g_psq [w * 64 + 32 + lane];
#pragma unroll
    for (int off = 16; off > 0; off >>= 1) {
        s += __shfl_down_sync(0xffffffffu, s, off);
        q += __shfl_down_sync(0xffffffffu, q, off);
    }
    if (lane == 0) { g_stats[2 * w] = s; g_stats[2 * w + 1] = q; }
}

__global__ void ln_finalize(float* __restrict__ y,
                            const float* __restrict__ lnw,
                            const float* __restrict__ lnb)
{
    int idx = blockIdx.x * 256 + threadIdx.x;
    int b   = idx >> 18;
    int sd4 = idx & ((1 << 18) - 1);
    const float invn = 1.0f / 1048576.0f;
    float mean = g_stats[2 * b] * invn;
    float var  = g_stats[2 * b + 1] * invn - mean * mean;
    float inv  = rsqrtf(var + 1e-5f);
    float4 v  = reinterpret_cast<float4*>(y)[idx];
    float4 w  = reinterpret_cast<const float4*>(lnw)[sd4];
    float4 bb = reinterpret_cast<const float4*>(lnb)[sd4];
    v.x = (v.x - mean) * inv * w.x + bb.x;
    v.y = (v.y - mean) * inv * w.y + bb.y;
    v.z = (v.z - mean) * inv * w.z + bb.z;
    v.w = (v.w - mean) * inv * w.w + bb.w;
    reinterpret_cast<float4*>(y)[idx] = v;
}

// ---------------------------------------------------------------------------
// kernel_launch
// ---------------------------------------------------------------------------
extern "C" void kernel_launch(void* const* d_in, const int* in_sizes, int n_in,
                              void* d_out, int out_size)
{
    const float* x    = (const float*)d_in[0];
    const float* W_qk = (const float*)d_in[1];
    const float* b_qk = (const float*)d_in[2];
    const float* W_v  = (const float*)d_in[3];
    const float* b_v  = (const float*)d_in[4];
    const float* W_o  = (const float*)d_in[5];
    const float* b_o  = (const float*)d_in[6];
    const float* ln_w = (const float*)d_in[7];
    const float* ln_b = (const float*)d_in[8];
    float* out = (float*)d_out;

    void *p_qk, *p_v, *p_ao, *p_xr, *p_wqk, *p_wv, *p_wo;
    cudaGetSymbolAddress(&p_qk,  g_qk);
    cudaGetSymbolAddress(&p_v,   g_v);
    cudaGetSymbolAddress(&p_ao,  g_ao);
    cudaGetSymbolAddress(&p_xr,  g_xr);
    cudaGetSymbolAddress(&p_wqk, g_wqk);
    cudaGetSymbolAddress(&p_wv,  g_wv);
    cudaGetSymbolAddress(&p_wo,  g_wo);

    cudaFuncSetAttribute(attn_tc_kernel, cudaFuncAttributeMaxDynamicSharedMemorySize,
                         AT_SMEM_BYTES);

    // 0) tf32 pre-rounding (x + weights) so cp.async raw copies are exact-rna
    round_tf32_kernel<<<(B_*S_*D_) / 1024, 256>>>((float*)p_xr, x);
    round_tf32_kernel<<<(NQK*D_)   / 1024, 256>>>((float*)p_wqk, W_qk);
    round_tf32_kernel<<<(NV*D_)    / 1024, 256>>>((float*)p_wv,  W_v);
    round_tf32_kernel<<<(D_*NV)    / 1024, 256>>>((float*)p_wo,  W_o);

    // 1) qk = x @ W_qk^T + b_qk   (8192 x 2048)
    tgemm_bias<<<dim3(NQK / 128, MROWS / 128), 256>>>((const float*)p_xr,
                                                      (const float*)p_wqk, b_qk,
                                                      (float*)p_qk, NQK);
    // 2) v  = x @ W_v^T + b_v     (8192 x 1024)
    tgemm_bias<<<dim3(NV / 128, MROWS / 128), 256>>>((const float*)p_xr,
                                                     (const float*)p_wv, b_v,
                                                     (float*)p_v, NV);
    // 3) repack into [b,h,s,64] (K/V tf32-rounded)
    repack_kernel<<<MROWS, 256>>>();
    // 4) flash attention — TF32 MMA + cp.async K/V pipeline
    attn_tc_kernel<<<dim3(S_ / 128, H_, B_), 256, AT_SMEM_BYTES>>>();
    // 5) O-proj + bias + residual + partial LN stats
    tgemm_oproj<<<dim3(NV / 128, MROWS / 128), 256>>>((const float*)p_ao,
                                                      (const float*)p_wo, b_o, x, out);
    // 6) reduce stats per batch
    stats_reduce<<<1, 256>>>();
    // 7) LayerNorm finalize
    ln_finalize<<<(B_ * S_ * D_ / 4) / 256, 256>>>(out, ln_w, ln_b);
}

// round 8
// speedup vs baseline: 1.2341x; 1.0681x over previous
#include <cuda_runtime.h>
#include <cuda_pipeline.h>
#include <math.h>

// Problem constants
#define B_   8
#define S_   1024
#define D_   1024
#define H_   16
#define KD_  64
#define VD_  64
#define NQK  2048          // H*KD*2
#define NV   1024          // H*VD
#define MROWS (B_*S_)      // 8192

// ---------------------------------------------------------------------------
// Scratch (static device arrays — no runtime allocation)
// ---------------------------------------------------------------------------
__device__ float g_qk [B_*S_*NQK];        // x @ W_qk^T + b
__device__ float g_v  [B_*S_*NV];         // x @ W_v^T  + b
__device__ float g_q  [B_*H_*S_*KD_];     // [b,h,s,kd] row-major
__device__ float g_k  [B_*H_*S_*KD_];     // frag-major tiles (tf32-rounded)
__device__ float g_vp [B_*H_*S_*VD_];     // frag-major tiles (tf32-rounded)
__device__ float g_ao [B_*S_*NV];         // attention out (tf32-rounded)
__device__ float g_xr [B_*S_*D_];         // tf32-rounded x
__device__ float g_wqk[NQK*D_];           // tf32-rounded W_qk
__device__ float g_wv [NV*D_];            // tf32-rounded W_v
__device__ float g_wo [D_*NV];            // tf32-rounded W_o
__device__ float g_psum[512];
__device__ float g_psq [512];
__device__ float g_stats[16];             // per-batch {sum, sumsq}

// ---------------------------------------------------------------------------
// TF32 helpers
// ---------------------------------------------------------------------------
__device__ __forceinline__ unsigned f2tf32(float f) {
    unsigned r;
    asm("cvt.rna.tf32.f32 %0, %1;" : "=r"(r) : "f"(f));
    return r;
}
__device__ __forceinline__ float rtf(float f) { return __uint_as_float(f2tf32(f)); }

__device__ __forceinline__ void mma_tf32(float& c0, float& c1, float& c2, float& c3,
                                         unsigned a0, unsigned a1, unsigned a2, unsigned a3,
                                         unsigned b0, unsigned b1) {
    asm volatile(
        "mma.sync.aligned.m16n8k8.row.col.f32.tf32.tf32.f32 "
        "{%0,%1,%2,%3}, {%4,%5,%6,%7}, {%8,%9}, {%0,%1,%2,%3};"
        : "+f"(c0), "+f"(c1), "+f"(c2), "+f"(c3)
        : "r"(a0), "r"(a1), "r"(a2), "r"(a3), "r"(b0), "r"(b1));
}

// FMA-pipe exp2 (no MUFU): deg-6 poly + exponent-field add
__device__ __forceinline__ float fexp2(float y) {
    y = fmaxf(y, -80.f);
    float tt = y + 12582912.f;                 // 1.5*2^23: round-to-nearest
    float f  = y - (tt - 12582912.f);          // f in [-0.5, 0.5]
    float p  = 1.5403530393381610e-4f;
    p = p * f + 1.3333558146428443e-3f;
    p = p * f + 9.6181291076284770e-3f;
    p = p * f + 5.5504108664821580e-2f;
    p = p * f + 2.4022650695910071e-1f;
    p = p * f + 6.9314718055994531e-1f;
    p = p * f + 1.0f;
    return __int_as_float(__float_as_int(p) + (__float_as_int(tt) << 23));
}

// ---------------------------------------------------------------------------
// tf32 pre-rounding pass (makes raw-byte cp.async == exact rna rounding)
// ---------------------------------------------------------------------------
__global__ void round_tf32_kernel(float* __restrict__ dst, const float* __restrict__ src)
{
    int i = blockIdx.x * 256 + threadIdx.x;
    float4 v = reinterpret_cast<const float4*>(src)[i];
    v.x = rtf(v.x); v.y = rtf(v.y); v.z = rtf(v.z); v.w = rtf(v.w);
    reinterpret_cast<float4*>(dst)[i] = v;
}

// ---------------------------------------------------------------------------
// TF32 tensor-core GEMM, cp.async 2-stage pipeline.
// C[M,N] = A[M,1024] @ W[N,1024]^T + bias[N]; A/W pre-rounded to tf32.
// 128x128 CTA, 8 warps (2M x 4N), BK=16, pitch 20 (conflict-free frags)
// ---------------------------------------------------------------------------
#define GP 20   // smem pitch in 32-bit words

__global__ __launch_bounds__(256, 2)
void tgemm_bias(const float* __restrict__ A, const float* __restrict__ W,
                const float* __restrict__ bias, float* __restrict__ C, int N)
{
    __shared__ unsigned As[2][128 * GP];
    __shared__ unsigned Ws[2][128 * GP];
    const int K = 1024;
    int tid = threadIdx.x;
    int warpId = tid >> 5, lane = tid & 31;
    int wm = warpId >> 2, wn = warpId & 3;
    int g = lane >> 2, t = lane & 3;
    int m0 = blockIdx.y * 128, n0 = blockIdx.x * 128;
    int r_ld = tid >> 2, c4_ld = (tid & 3) * 4;

    float c[4][4][4];
#pragma unroll
    for (int i = 0; i < 4; i++)
#pragma unroll
        for (int j = 0; j < 4; j++)
#pragma unroll
            for (int f = 0; f < 4; f++) c[i][j][f] = 0.f;

    auto load_stage = [&](int st, int k0) {
#pragma unroll
        for (int l = 0; l < 2; l++) {
            int r = r_ld + l * 64;
            __pipeline_memcpy_async(&As[st][r * GP + c4_ld],
                                    &A[(size_t)(m0 + r) * K + k0 + c4_ld], 16);
            __pipeline_memcpy_async(&Ws[st][r * GP + c4_ld],
                                    &W[(size_t)(n0 + r) * K + k0 + c4_ld], 16);
        }
    };

    load_stage(0, 0);
    __pipeline_commit();

    int cur = 0;
    for (int k0 = 0; k0 < K; k0 += 16) {
        if (k0 + 16 < K) {
            load_stage(cur ^ 1, k0 + 16);
            __pipeline_commit();
            __pipeline_wait_prior(1);
        } else {
            __pipeline_wait_prior(0);
        }
        __syncthreads();

#pragma unroll
        for (int ks = 0; ks < 16; ks += 8) {
            unsigned af[4][4], bf[4][2];
#pragma unroll
            for (int tm = 0; tm < 4; tm++) {
                int row = wm * 64 + tm * 16 + g;
                af[tm][0] = As[cur][row * GP + ks + t];
                af[tm][1] = As[cur][(row + 8) * GP + ks + t];
                af[tm][2] = As[cur][row * GP + ks + 4 + t];
                af[tm][3] = As[cur][(row + 8) * GP + ks + 4 + t];
            }
#pragma unroll
            for (int tn = 0; tn < 4; tn++) {
                int rowb = wn * 32 + tn * 8 + g;
                bf[tn][0] = Ws[cur][rowb * GP + ks + t];
                bf[tn][1] = Ws[cur][rowb * GP + ks + 4 + t];
            }
#pragma unroll
            for (int tm = 0; tm < 4; tm++)
#pragma unroll
                for (int tn = 0; tn < 4; tn++)
                    mma_tf32(c[tm][tn][0], c[tm][tn][1], c[tm][tn][2], c[tm][tn][3],
                             af[tm][0], af[tm][1], af[tm][2], af[tm][3],
                             bf[tn][0], bf[tn][1]);
        }
        __syncthreads();
        cur ^= 1;
    }

#pragma unroll
    for (int tm = 0; tm < 4; tm++) {
        int row = m0 + wm * 64 + tm * 16 + g;
#pragma unroll
        for (int tn = 0; tn < 4; tn++) {
            int col = n0 + wn * 32 + tn * 8 + 2 * t;
            float2 o0, o1;
            o0.x = c[tm][tn][0] + bias[col];
            o0.y = c[tm][tn][1] + bias[col + 1];
            o1.x = c[tm][tn][2] + bias[col];
            o1.y = c[tm][tn][3] + bias[col + 1];
            *reinterpret_cast<float2*>(&C[(size_t)row * N + col])       = o0;
            *reinterpret_cast<float2*>(&C[(size_t)(row + 8) * N + col]) = o1;
        }
    }
}

// ---------------------------------------------------------------------------
// O-projection (pipelined TF32 MMA): C = A @ W_o^T + b_o + x, + LN partials
// ---------------------------------------------------------------------------
__global__ __launch_bounds__(256, 2)
void tgemm_oproj(const float* __restrict__ A, const float* __restrict__ W,
                 const float* __restrict__ bias, const float* __restrict__ x,
                 float* __restrict__ C)
{
    __shared__ unsigned As[2][128 * GP];
    __shared__ unsigned Ws[2][128 * GP];
    const int K = 1024, N = 1024;
    int tid = threadIdx.x;
    int warpId = tid >> 5, lane = tid & 31;
    int wm = warpId >> 2, wn = warpId & 3;
    int g = lane >> 2, t = lane & 3;
    int m0 = blockIdx.y * 128, n0 = blockIdx.x * 128;
    int r_ld = tid >> 2, c4_ld = (tid & 3) * 4;

    float c[4][4][4];
#pragma unroll
    for (int i = 0; i < 4; i++)
#pragma unroll
        for (int j = 0; j < 4; j++)
#pragma unroll
            for (int f = 0; f < 4; f++) c[i][j][f] = 0.f;

    auto load_stage = [&](int st, int k0) {
#pragma unroll
        for (int l = 0; l < 2; l++) {
            int r = r_ld + l * 64;
            __pipeline_memcpy_async(&As[st][r * GP + c4_ld],
                                    &A[(size_t)(m0 + r) * K + k0 + c4_ld], 16);
            __pipeline_memcpy_async(&Ws[st][r * GP + c4_ld],
                                    &W[(size_t)(n0 + r) * K + k0 + c4_ld], 16);
        }
    };

    load_stage(0, 0);
    __pipeline_commit();

    int cur = 0;
    for (int k0 = 0; k0 < K; k0 += 16) {
        if (k0 + 16 < K) {
            load_stage(cur ^ 1, k0 + 16);
            __pipeline_commit();
            __pipeline_wait_prior(1);
        } else {
            __pipeline_wait_prior(0);
        }
        __syncthreads();

#pragma unroll
        for (int ks = 0; ks < 16; ks += 8) {
            unsigned af[4][4], bf[4][2];
#pragma unroll
            for (int tm = 0; tm < 4; tm++) {
                int row = wm * 64 + tm * 16 + g;
                af[tm][0] = As[cur][row * GP + ks + t];
                af[tm][1] = As[cur][(row + 8) * GP + ks + t];
                af[tm][2] = As[cur][row * GP + ks + 4 + t];
                af[tm][3] = As[cur][(row + 8) * GP + ks + 4 + t];
            }
#pragma unroll
            for (int tn = 0; tn < 4; tn++) {
                int rowb = wn * 32 + tn * 8 + g;
                bf[tn][0] = Ws[cur][rowb * GP + ks + t];
                bf[tn][1] = Ws[cur][rowb * GP + ks + 4 + t];
            }
#pragma unroll
            for (int tm = 0; tm < 4; tm++)
#pragma unroll
                for (int tn = 0; tn < 4; tn++)
                    mma_tf32(c[tm][tn][0], c[tm][tn][1], c[tm][tn][2], c[tm][tn][3],
                             af[tm][0], af[tm][1], af[tm][2], af[tm][3],
                             bf[tn][0], bf[tn][1]);
        }
        __syncthreads();
        cur ^= 1;
    }

    float lsum = 0.f, lsq = 0.f;
#pragma unroll
    for (int tm = 0; tm < 4; tm++) {
        int row = m0 + wm * 64 + tm * 16 + g;
#pragma unroll
        for (int tn = 0; tn < 4; tn++) {
            int col = n0 + wn * 32 + tn * 8 + 2 * t;
            float2 x0 = *reinterpret_cast<const float2*>(&x[(size_t)row * N + col]);
            float2 x1 = *reinterpret_cast<const float2*>(&x[(size_t)(row + 8) * N + col]);
            float2 o0, o1;
            o0.x = c[tm][tn][0] + bias[col]     + x0.x;
            o0.y = c[tm][tn][1] + bias[col + 1] + x0.y;
            o1.x = c[tm][tn][2] + bias[col]     + x1.x;
            o1.y = c[tm][tn][3] + bias[col + 1] + x1.y;
            *reinterpret_cast<float2*>(&C[(size_t)row * N + col])       = o0;
            *reinterpret_cast<float2*>(&C[(size_t)(row + 8) * N + col]) = o1;
            lsum += o0.x + o0.y + o1.x + o1.y;
            lsq  += o0.x*o0.x + o0.y*o0.y + o1.x*o1.x + o1.y*o1.y;
        }
    }
#pragma unroll
    for (int off = 16; off > 0; off >>= 1) {
        lsum += __shfl_down_sync(0xffffffffu, lsum, off);
        lsq  += __shfl_down_sync(0xffffffffu, lsq,  off);
    }
    __shared__ float rs[8], rq[8];
    if (lane == 0) { rs[warpId] = lsum; rq[warpId] = lsq; }
    __syncthreads();
    if (tid == 0) {
        float s = 0.f, q = 0.f;
#pragma unroll
        for (int w = 0; w < 8; w++) { s += rs[w]; q += rq[w]; }
        int p = blockIdx.y * 8 + blockIdx.x;   // 0..511, 64 per batch
        g_psum[p] = s; g_psq[p] = q;
    }
}

// ---------------------------------------------------------------------------
// Repack: de-interleave qk/v. Q -> [b,h,s,64] row-major.
// K,V -> MMA-fragment-major 16KB tiles:
//   tile index = bh*16 + (s>>6); within tile:
//   word = ((k*4 + n2)*32 + lane)*4 + w,  lane = g*4 + t,  w = npar*2 + hi
//   K: (j=s, kd):  n=jl>>3,g=jl&7 ; k=kd>>3, t=kd&3, hi=(kd>>2)&1
//   V: (j=s, vd):  k=jl>>3, t=jl&3, hi=(jl>>2)&1 ; n=vd>>3, g=vd&7
// so one uint4 per lane = {b0,b1} frags for n=2*n2 and n=2*n2+1.
// ---------------------------------------------------------------------------
__global__ void repack_kernel()
{
    __shared__ float sqk[2048 + 64];
    __shared__ float sv [1024 + 32];
    int bs = blockIdx.x;            // 0..8191
    int b = bs >> 10, s = bs & 1023;
    int tid = threadIdx.x;          // 256
    const float* qkrow = g_qk + (size_t)bs * NQK;
    const float* vrow  = g_v  + (size_t)bs * NV;
    for (int c = tid; c < 2048; c += 256) sqk[c + (c >> 5)] = qkrow[c];
    for (int c = tid; c < 1024; c += 256) sv [c + (c >> 5)] = vrow[c];
    __syncthreads();

    int jt = s >> 6, jl = s & 63;
    // K per-row constants (j = s)
    int kn  = jl >> 3, kg = jl & 7;
    int kn2 = kn >> 1, knp = kn & 1;
    // V per-row constants (j = s)
    int vt = jl & 3, vhi = (jl >> 2) & 1, vk = jl >> 3;

    for (int idx = tid; idx < 1024; idx += 256) {
        int h = idx >> 6, d = idx & 63;       // d = kd (for q,k) or vd (for v)
        int cq = d * 32 + h;
        int ck = cq + 16;
        int cv = d * 16 + h;
        size_t bh = (size_t)(b * H_ + h);
        // Q row-major
        g_q[(bh * S_ + s) * 64 + d] = sqk[cq + (cq >> 5)];
        size_t tbase = (bh * 16 + jt) * 4096;
        // K frag-major: k/t/hi from kd
        {
            int k = d >> 3, t_ = d & 3, hi = (d >> 2) & 1;
            int lanek = kg * 4 + t_;
            int w = knp * 2 + hi;
            g_k[tbase + (size_t)(((k * 4 + kn2) * 32 + lanek) * 4 + w)] =
                rtf(sqk[ck + (ck >> 5)]);
        }
        // V frag-major: n/g from vd
        {
            int n = d >> 3, gg = d & 7;
            int n2 = n >> 1, npar = n & 1;
            int lanev = gg * 4 + vt;
            int w = npar * 2 + vhi;
            g_vp[tbase + (size_t)(((vk * 4 + n2) * 32 + lanev) * 4 + w)] =
                rtf(sv[cv + (cv >> 5)]);
        }
    }
}

// ---------------------------------------------------------------------------
// TF32 tensor-core flash attention, cp.async 2-stage K/V pipeline.
// K/V staged as fragment-major 16KB tiles -> one LDS.128 per (k,n2) frag pair.
// CTA = (b, h, 128 q-rows); 8 warps, warp owns 16 rows; j-tiles of 64.
// ---------------------------------------------------------------------------
#define PA 68
#define TILE_W 4096                      // words per frag-major K or V tile
#define AT_SMEM_BYTES ((128 * PA + 4 * TILE_W) * 4)   // Q/P + 2xK + 2xV

__global__ __launch_bounds__(256, 2)
void attn_tc_kernel()
{
    extern __shared__ unsigned smu[];
    unsigned* Qs = smu;                            // [128][PA]; becomes Ps
    unsigned* Ks = smu + 128 * PA;                 // [2][4096]
    unsigned* Vs = smu + 128 * PA + 2 * TILE_W;    // [2][4096]

    int tid  = threadIdx.x;
    int warp = tid >> 5, lane = tid & 31;
    int g = lane >> 2, t = lane & 3;
    int i0 = blockIdx.x * 128;
    int h  = blockIdx.y, b = blockIdx.z;
    int bh = b * H_ + h;
    const float* Qb = g_q  + ((size_t)bh * S_ + i0) * KD_;
    const float* Kb = g_k  + (size_t)bh * 16 * TILE_W;   // frag-major tiles
    const float* Vb = g_vp + (size_t)bh * 16 * TILE_W;
    const float QSCL = 0.125f * 1.4426950408889634f;  // 1/sqrt(64) * log2(e)

    // stage one frag-major K and V tile: 1024 linear float4 chunks each
    auto load_kv = [&](int st, int jt) {
        const float* Kt = Kb + (size_t)jt * TILE_W;
        const float* Vt = Vb + (size_t)jt * TILE_W;
#pragma unroll
        for (int l = 0; l < 4; l++) {
            int idx = tid + l * 256;            // 0..1023
            __pipeline_memcpy_async(&Ks[st * TILE_W + idx * 4], &Kt[idx * 4], 16);
            __pipeline_memcpy_async(&Vs[st * TILE_W + idx * 4], &Vt[idx * 4], 16);
        }
    };

    // prefetch first K/V tile, then stage Q while it flies
    load_kv(0, 0);
    __pipeline_commit();

    for (int idx = tid; idx < 128 * 16; idx += 256) {
        int r = idx >> 4, c4 = (idx & 15) * 4;
        float4 q = *reinterpret_cast<const float4*>(&Qb[(size_t)r * 64 + c4]);
        Qs[r * PA + c4 + 0] = f2tf32(q.x * QSCL);
        Qs[r * PA + c4 + 1] = f2tf32(q.y * QSCL);
        Qs[r * PA + c4 + 2] = f2tf32(q.z * QSCL);
        Qs[r * PA + c4 + 3] = f2tf32(q.w * QSCL);
    }
    __syncthreads();

    int wr = warp * 16;
    unsigned qf[8][4];
#pragma unroll
    for (int k = 0; k < 8; k++) {
        qf[k][0] = Qs[(wr + g)     * PA + k * 8 + t];
        qf[k][1] = Qs[(wr + g + 8) * PA + k * 8 + t];
        qf[k][2] = Qs[(wr + g)     * PA + k * 8 + 4 + t];
        qf[k][3] = Qs[(wr + g + 8) * PA + k * 8 + 4 + t];
    }
    __syncthreads();            // Qs region now free -> becomes Ps
    unsigned* Ps = Qs;

    float accO[8][4];
#pragma unroll
    for (int n = 0; n < 8; n++)
#pragma unroll
        for (int f = 0; f < 4; f++) accO[n][f] = 0.f;
    float m0 = -1e30f, m1 = -1e30f, l0 = 0.f, l1 = 0.f;

    int cur = 0;
    for (int jt = 0; jt < 16; jt++) {
        if (jt + 1 < 16) {
            load_kv(cur ^ 1, jt + 1);
            __pipeline_commit();
            __pipeline_wait_prior(1);
        } else {
            __pipeline_wait_prior(0);
        }
        __syncthreads();
        const uint4* K4 = reinterpret_cast<const uint4*>(Ks + cur * TILE_W);
        const uint4* V4 = reinterpret_cast<const uint4*>(Vs + cur * TILE_W);

        // S = Q K^T  (warp: 16 x 64), one LDS.128 per (k, n2)
        float sacc[8][4];
#pragma unroll
        for (int n = 0; n < 8; n++)
#pragma unroll
            for (int f = 0; f < 4; f++) sacc[n][f] = 0.f;
#pragma unroll
        for (int k = 0; k < 8; k++) {
#pragma unroll
            for (int n2 = 0; n2 < 4; n2++) {
                uint4 bb = K4[(k * 4 + n2) * 32 + lane];
                mma_tf32(sacc[2*n2][0], sacc[2*n2][1], sacc[2*n2][2], sacc[2*n2][3],
                         qf[k][0], qf[k][1], qf[k][2], qf[k][3], bb.x, bb.y);
                mma_tf32(sacc[2*n2+1][0], sacc[2*n2+1][1], sacc[2*n2+1][2], sacc[2*n2+1][3],
                         qf[k][0], qf[k][1], qf[k][2], qf[k][3], bb.z, bb.w);
            }
        }

        // online softmax (rows wr+g, wr+g+8), exp2 on FMA pipe
        float tm0 = -1e30f, tm1 = -1e30f;
#pragma unroll
        for (int n = 0; n < 8; n++) {
            tm0 = fmaxf(tm0, fmaxf(sacc[n][0], sacc[n][1]));
            tm1 = fmaxf(tm1, fmaxf(sacc[n][2], sacc[n][3]));
        }
        tm0 = fmaxf(tm0, __shfl_xor_sync(0xffffffffu, tm0, 1));
        tm0 = fmaxf(tm0, __shfl_xor_sync(0xffffffffu, tm0, 2));
        tm1 = fmaxf(tm1, __shfl_xor_sync(0xffffffffu, tm1, 1));
        tm1 = fmaxf(tm1, __shfl_xor_sync(0xffffffffu, tm1, 2));
        float mn0 = fmaxf(m0, tm0), mn1 = fmaxf(m1, tm1);
        float sc0 = fexp2(m0 - mn0), sc1 = fexp2(m1 - mn1);
        float ps0 = 0.f, ps1 = 0.f;
#pragma unroll
        for (int n = 0; n < 8; n++) {
            float p0 = fexp2(sacc[n][0] - mn0);
            float p1 = fexp2(sacc[n][1] - mn0);
            float p2 = fexp2(sacc[n][2] - mn1);
            float p3 = fexp2(sacc[n][3] - mn1);
            ps0 += p0 + p1; ps1 += p2 + p3;
            *reinterpret_cast<uint2*>(&Ps[(wr + g)     * PA + n * 8 + 2 * t]) =
                make_uint2(f2tf32(p0), f2tf32(p1));
            *reinterpret_cast<uint2*>(&Ps[(wr + g + 8) * PA + n * 8 + 2 * t]) =
                make_uint2(f2tf32(p2), f2tf32(p3));
            accO[n][0] *= sc0; accO[n][1] *= sc0;
            accO[n][2] *= sc1; accO[n][3] *= sc1;
        }
        ps0 += __shfl_xor_sync(0xffffffffu, ps0, 1);
        ps0 += __shfl_xor_sync(0xffffffffu, ps0, 2);
        ps1 += __shfl_xor_sync(0xffffffffu, ps1, 1);
        ps1 += __shfl_xor_sync(0xffffffffu, ps1, 2);
        l0 = l0 * sc0 + ps0;
        l1 = l1 * sc1 + ps1;
        m0 = mn0; m1 = mn1;
        __syncwarp();   // P staging is warp-private

        // O += P V : A-frags from Ps, one LDS.128 per (k, n2) for V frags
#pragma unroll
        for (int k = 0; k < 8; k++) {
            unsigned a0 = Ps[(wr + g)     * PA + k * 8 + t];
            unsigned a1 = Ps[(wr + g + 8) * PA + k * 8 + t];
            unsigned a2 = Ps[(wr + g)     * PA + k * 8 + 4 + t];
            unsigned a3 = Ps[(wr + g + 8) * PA + k * 8 + 4 + t];
#pragma unroll
            for (int n2 = 0; n2 < 4; n2++) {
                uint4 bb = V4[(k * 4 + n2) * 32 + lane];
                mma_tf32(accO[2*n2][0], accO[2*n2][1], accO[2*n2][2], accO[2*n2][3],
                         a0, a1, a2, a3, bb.x, bb.y);
                mma_tf32(accO[2*n2+1][0], accO[2*n2+1][1], accO[2*n2+1][2], accO[2*n2+1][3],
                         a0, a1, a2, a3, bb.z, bb.w);
            }
        }
        __syncthreads();  // stage cur may be overwritten next iteration
        cur ^= 1;
    }

    // epilogue: normalize, round to tf32 (oproj raw-copies it), write
    float inv0 = 1.f / l0, inv1 = 1.f / l1;
    int row0 = i0 + wr + g, row1 = row0 + 8;
#pragma unroll
    for (int n = 0; n < 8; n++) {
        int col = h * 64 + n * 8 + 2 * t;
        float2 o0, o1;
        o0.x = rtf(accO[n][0] * inv0); o0.y = rtf(accO[n][1] * inv0);
        o1.x = rtf(accO[n][2] * inv1); o1.y = rtf(accO[n][3] * inv1);
        *reinterpret_cast<float2*>(&g_ao[(size_t)(b * S_ + row0) * NV + col]) = o0;
        *reinterpret_cast<float2*>(&g_ao[(size_t)(b * S_ + row1) * NV + col]) = o1;
    }
}

// ---------------------------------------------------------------------------
// LN stats reduce + finalize
// ---------------------------------------------------------------------------
__global__ void stats_reduce()
{
    int w = threadIdx.x >> 5, lane = threadIdx.x & 31;
    float s = g_psum[w * 64 + lane] + g_psum[w * 64 + 32 + lane];
    float q = g_psq [w * 64 + lane] + g_psq [w * 64 + 32 + lane];
#pragma unroll
    for (int off = 16; off > 0; off >>= 1) {
        s += __shfl_down_sync(0xffffffffu, s, off);
        q += __shfl_down_sync(0xffffffffu, q, off);
    }
    if (lane == 0) { g_stats[2 * w] = s; g_stats[2 * w + 1] = q; }
}

__global__ void ln_finalize(float* __restrict__ y,
                            const float* __restrict__ lnw,
                            const float* __restrict__ lnb)
{
    int idx = blockIdx.x * 256 + threadIdx.x;
    int b   = idx >> 18;
    int sd4 = idx & ((1 << 18) - 1);
    const float invn = 1.0f / 1048576.0f;
    float mean = g_stats[2 * b] * invn;
    float var  = g_stats[2 * b + 1] * invn - mean * mean;
    float inv  = rsqrtf(var + 1e-5f);
    float4 v  = reinterpret_cast<float4*>(y)[idx];
    float4 w  = reinterpret_cast<const float4*>(lnw)[sd4];
    float4 bb = reinterpret_cast<const float4*>(lnb)[sd4];
    v.x = (v.x - mean) * inv * w.x + bb.x;
    v.y = (v.y - mean) * inv * w.y + bb.y;
    v.z = (v.z - mean) * inv * w.z + bb.z;
    v.w = (v.w - mean) * inv * w.w + bb.w;
    reinterpret_cast<float4*>(y)[idx] = v;
}

// ---------------------------------------------------------------------------
// kernel_launch
// ---------------------------------------------------------------------------
extern "C" void kernel_launch(void* const* d_in, const int* in_sizes, int n_in,
                              void* d_out, int out_size)
{
    const float* x    = (const float*)d_in[0];
    const float* W_qk = (const float*)d_in[1];
    const float* b_qk = (const float*)d_in[2];
    const float* W_v  = (const float*)d_in[3];
    const float* b_v  = (const float*)d_in[4];
    const float* W_o  = (const float*)d_in[5];
    const float* b_o  = (const float*)d_in[6];
    const float* ln_w = (const float*)d_in[7];
    const float* ln_b = (const float*)d_in[8];
    float* out = (float*)d_out;

    void *p_qk, *p_v, *p_ao, *p_xr, *p_wqk, *p_wv, *p_wo;
    cudaGetSymbolAddress(&p_qk,  g_qk);
    cudaGetSymbolAddress(&p_v,   g_v);
    cudaGetSymbolAddress(&p_ao,  g_ao);
    cudaGetSymbolAddress(&p_xr,  g_xr);
    cudaGetSymbolAddress(&p_wqk, g_wqk);
    cudaGetSymbolAddress(&p_wv,  g_wv);
    cudaGetSymbolAddress(&p_wo,  g_wo);

    cudaFuncSetAttribute(attn_tc_kernel, cudaFuncAttributeMaxDynamicSharedMemorySize,
                         AT_SMEM_BYTES);

    // 0) tf32 pre-rounding (x + weights) so cp.async raw copies are exact-rna
    round_tf32_kernel<<<(B_*S_*D_) / 1024, 256>>>((float*)p_xr, x);
    round_tf32_kernel<<<(NQK*D_)   / 1024, 256>>>((float*)p_wqk, W_qk);
    round_tf32_kernel<<<(NV*D_)    / 1024, 256>>>((float*)p_wv,  W_v);
    round_tf32_kernel<<<(D_*NV)    / 1024, 256>>>((float*)p_wo,  W_o);

    // 1) qk = x @ W_qk^T + b_qk   (8192 x 2048)
    tgemm_bias<<<dim3(NQK / 128, MROWS / 128), 256>>>((const float*)p_xr,
                                                      (const float*)p_wqk, b_qk,
                                                      (float*)p_qk, NQK);
    // 2) v  = x @ W_v^T + b_v     (8192 x 1024)
    tgemm_bias<<<dim3(NV / 128, MROWS / 128), 256>>>((const float*)p_xr,
                                                     (const float*)p_wv, b_v,
                                                     (float*)p_v, NV);
    // 3) repack: Q row-major; K/V frag-major tiles (tf32-rounded)
    repack_kernel<<<MROWS, 256>>>();
    // 4) flash attention — TF32 MMA, frag-major K/V, cp.async pipeline
    attn_tc_kernel<<<dim3(S_ / 128, H_, B_), 256, AT_SMEM_BYTES>>>();
    // 5) O-proj + bias + residual + partial LN stats
    tgemm_oproj<<<dim3(NV / 128, MROWS / 128), 256>>>((const float*)p_ao,
                                                      (const float*)p_wo, b_o, x, out);
    // 6) reduce stats per batch
    stats_reduce<<<1, 256>>>();
    // 7) LayerNorm finalize
    ln_finalize<<<(B_ * S_ * D_ / 4) / 256, 256>>>(out, ln_w, ln_b);
}

// round 9
// speedup vs baseline: 1.7461x; 1.4149x over previous
#include <cuda_runtime.h>
#include <cuda_pipeline.h>
#include <cuda_bf16.h>
#include <math.h>

// Problem constants
#define B_   8
#define S_   1024
#define D_   1024
#define H_   16
#define KD_  64
#define VD_  64
#define NQK  2048          // H*KD*2
#define NV   1024          // H*VD
#define MROWS (B_*S_)      // 8192

// ---------------------------------------------------------------------------
// Scratch (static device arrays — no runtime allocation)
// ---------------------------------------------------------------------------
__device__ float g_qk [B_*S_*NQK];        // x @ W_qk^T + b   (f32)
__device__ float g_v  [B_*S_*NV];         // x @ W_v^T  + b   (f32)
__device__ float g_q  [B_*H_*S_*KD_];     // [b,h,s,kd] row-major
__device__ float g_k  [B_*H_*S_*KD_];     // frag-major tiles (tf32-rounded)
__device__ float g_vp [B_*H_*S_*VD_];     // frag-major tiles (tf32-rounded)
__device__ __nv_bfloat16 g_aoh[B_*S_*NV]; // attention out (bf16)
__device__ __nv_bfloat16 g_xh [B_*S_*D_]; // bf16 x
__device__ __nv_bfloat16 g_wqkh[NQK*D_];  // bf16 W_qk
__device__ __nv_bfloat16 g_wvh [NV*D_];   // bf16 W_v
__device__ __nv_bfloat16 g_woh [D_*NV];   // bf16 W_o
__device__ float g_psum[512];
__device__ float g_psq [512];
__device__ float g_stats[16];             // per-batch {sum, sumsq}

// ---------------------------------------------------------------------------
// MMA helpers
// ---------------------------------------------------------------------------
__device__ __forceinline__ unsigned f2tf32(float f) {
    unsigned r;
    asm("cvt.rna.tf32.f32 %0, %1;" : "=r"(r) : "f"(f));
    return r;
}
__device__ __forceinline__ float rtf(float f) { return __uint_as_float(f2tf32(f)); }

__device__ __forceinline__ void mma_tf32(float& c0, float& c1, float& c2, float& c3,
                                         unsigned a0, unsigned a1, unsigned a2, unsigned a3,
                                         unsigned b0, unsigned b1) {
    asm volatile(
        "mma.sync.aligned.m16n8k8.row.col.f32.tf32.tf32.f32 "
        "{%0,%1,%2,%3}, {%4,%5,%6,%7}, {%8,%9}, {%0,%1,%2,%3};"
        : "+f"(c0), "+f"(c1), "+f"(c2), "+f"(c3)
        : "r"(a0), "r"(a1), "r"(a2), "r"(a3), "r"(b0), "r"(b1));
}

// bf16 m16n8k16: a regs hold {A[g][2t],A[g][2t+1]} etc. (little-endian pairs)
__device__ __forceinline__ void mma_bf16(float& c0, float& c1, float& c2, float& c3,
                                         unsigned a0, unsigned a1, unsigned a2, unsigned a3,
                                         unsigned b0, unsigned b1) {
    asm volatile(
        "mma.sync.aligned.m16n8k16.row.col.f32.bf16.bf16.f32 "
        "{%0,%1,%2,%3}, {%4,%5,%6,%7}, {%8,%9}, {%0,%1,%2,%3};"
        : "+f"(c0), "+f"(c1), "+f"(c2), "+f"(c3)
        : "r"(a0), "r"(a1), "r"(a2), "r"(a3), "r"(b0), "r"(b1));
}

// FMA-pipe exp2 (no MUFU): deg-6 poly + exponent-field add
__device__ __forceinline__ float fexp2(float y) {
    y = fmaxf(y, -80.f);
    float tt = y + 12582912.f;                 // 1.5*2^23: round-to-nearest
    float f  = y - (tt - 12582912.f);          // f in [-0.5, 0.5]
    float p  = 1.5403530393381610e-4f;
    p = p * f + 1.3333558146428443e-3f;
    p = p * f + 9.6181291076284770e-3f;
    p = p * f + 5.5504108664821580e-2f;
    p = p * f + 2.4022650695910071e-1f;
    p = p * f + 6.9314718055994531e-1f;
    p = p * f + 1.0f;
    return __int_as_float(__float_as_int(p) + (__float_as_int(tt) << 23));
}

// ---------------------------------------------------------------------------
// bf16 packing pass (rn rounding; cp.async then copies raw bf16)
// ---------------------------------------------------------------------------
__global__ void pack_bf16_kernel(__nv_bfloat16* __restrict__ dst,
                                 const float* __restrict__ src)
{
    int i = blockIdx.x * 256 + threadIdx.x;
    float4 v = reinterpret_cast<const float4*>(src)[i];
    __nv_bfloat162 lo = __floats2bfloat162_rn(v.x, v.y);
    __nv_bfloat162 hi = __floats2bfloat162_rn(v.z, v.w);
    uint2 o;
    o.x = *reinterpret_cast<unsigned*>(&lo);
    o.y = *reinterpret_cast<unsigned*>(&hi);
    reinterpret_cast<uint2*>(dst)[i] = o;
}

// ---------------------------------------------------------------------------
// bf16 tensor-core GEMM, cp.async 2-stage pipeline.
// C[M,N] = A[M,1024] @ W[N,1024]^T + bias[N]; A/W bf16.
// 128x128 CTA, 8 warps (2M x 4N), BK=32, m16n8k16.
// Smem rows = 16 words (32 bf16), pitch 20 words -> conflict-free frag LDS.
// ---------------------------------------------------------------------------
#define HP 20   // smem pitch in 32-bit words

__global__ __launch_bounds__(256, 2)
void hgemm_bias(const __nv_bfloat16* __restrict__ A, const __nv_bfloat16* __restrict__ W,
                const float* __restrict__ bias, float* __restrict__ C, int N)
{
    __shared__ unsigned As[2][128 * HP];
    __shared__ unsigned Ws[2][128 * HP];
    const int K = 1024;
    int tid = threadIdx.x;
    int warpId = tid >> 5, lane = tid & 31;
    int wm = warpId >> 2, wn = warpId & 3;
    int g = lane >> 2, t = lane & 3;
    int m0 = blockIdx.y * 128, n0 = blockIdx.x * 128;

    float c[4][4][4];
#pragma unroll
    for (int i = 0; i < 4; i++)
#pragma unroll
        for (int j = 0; j < 4; j++)
#pragma unroll
            for (int f = 0; f < 4; f++) c[i][j][f] = 0.f;

    // 512 16B-chunks per array per stage (128 rows x 4 chunks)
    auto load_stage = [&](int st, int k0) {
#pragma unroll
        for (int l = 0; l < 2; l++) {
            int idx = tid + l * 256;            // 0..511
            int r   = idx >> 2;                 // 0..127
            int cw  = (idx & 3) * 4;            // word offset 0,4,8,12
            __pipeline_memcpy_async(&As[st][r * HP + cw],
                                    &A[(size_t)(m0 + r) * K + k0 + cw * 2], 16);
            __pipeline_memcpy_async(&Ws[st][r * HP + cw],
                                    &W[(size_t)(n0 + r) * K + k0 + cw * 2], 16);
        }
    };

    load_stage(0, 0);
    __pipeline_commit();

    int cur = 0;
    for (int k0 = 0; k0 < K; k0 += 32) {
        if (k0 + 32 < K) {
            load_stage(cur ^ 1, k0 + 32);
            __pipeline_commit();
            __pipeline_wait_prior(1);
        } else {
            __pipeline_wait_prior(0);
        }
        __syncthreads();

#pragma unroll
        for (int ks = 0; ks < 2; ks++) {       // two k16 steps per BK=32
            unsigned af[4][4], bf[4][2];
#pragma unroll
            for (int tm = 0; tm < 4; tm++) {
                int row = wm * 64 + tm * 16 + g;
                af[tm][0] = As[cur][row * HP + ks * 8 + t];
                af[tm][1] = As[cur][(row + 8) * HP + ks * 8 + t];
                af[tm][2] = As[cur][row * HP + ks * 8 + 4 + t];
                af[tm][3] = As[cur][(row + 8) * HP + ks * 8 + 4 + t];
            }
#pragma unroll
            for (int tn = 0; tn < 4; tn++) {
                int rowb = wn * 32 + tn * 8 + g;
                bf[tn][0] = Ws[cur][rowb * HP + ks * 8 + t];
                bf[tn][1] = Ws[cur][rowb * HP + ks * 8 + 4 + t];
            }
#pragma unroll
            for (int tm = 0; tm < 4; tm++)
#pragma unroll
                for (int tn = 0; tn < 4; tn++)
                    mma_bf16(c[tm][tn][0], c[tm][tn][1], c[tm][tn][2], c[tm][tn][3],
                             af[tm][0], af[tm][1], af[tm][2], af[tm][3],
                             bf[tn][0], bf[tn][1]);
        }
        __syncthreads();
        cur ^= 1;
    }

#pragma unroll
    for (int tm = 0; tm < 4; tm++) {
        int row = m0 + wm * 64 + tm * 16 + g;
#pragma unroll
        for (int tn = 0; tn < 4; tn++) {
            int col = n0 + wn * 32 + tn * 8 + 2 * t;
            float2 o0, o1;
            o0.x = c[tm][tn][0] + bias[col];
            o0.y = c[tm][tn][1] + bias[col + 1];
            o1.x = c[tm][tn][2] + bias[col];
            o1.y = c[tm][tn][3] + bias[col + 1];
            *reinterpret_cast<float2*>(&C[(size_t)row * N + col])       = o0;
            *reinterpret_cast<float2*>(&C[(size_t)(row + 8) * N + col]) = o1;
        }
    }
}

// ---------------------------------------------------------------------------
// O-projection (bf16 MMA): C = A @ W_o^T + b_o + x, + LN partials
// ---------------------------------------------------------------------------
__global__ __launch_bounds__(256, 2)
void hgemm_oproj(const __nv_bfloat16* __restrict__ A, const __nv_bfloat16* __restrict__ W,
                 const float* __restrict__ bias, const float* __restrict__ x,
                 float* __restrict__ C)
{
    __shared__ unsigned As[2][128 * HP];
    __shared__ unsigned Ws[2][128 * HP];
    const int K = 1024, N = 1024;
    int tid = threadIdx.x;
    int warpId = tid >> 5, lane = tid & 31;
    int wm = warpId >> 2, wn = warpId & 3;
    int g = lane >> 2, t = lane & 3;
    int m0 = blockIdx.y * 128, n0 = blockIdx.x * 128;

    float c[4][4][4];
#pragma unroll
    for (int i = 0; i < 4; i++)
#pragma unroll
        for (int j = 0; j < 4; j++)
#pragma unroll
            for (int f = 0; f < 4; f++) c[i][j][f] = 0.f;

    auto load_stage = [&](int st, int k0) {
#pragma unroll
        for (int l = 0; l < 2; l++) {
            int idx = tid + l * 256;
            int r   = idx >> 2;
            int cw  = (idx & 3) * 4;
            __pipeline_memcpy_async(&As[st][r * HP + cw],
                                    &A[(size_t)(m0 + r) * K + k0 + cw * 2], 16);
            __pipeline_memcpy_async(&Ws[st][r * HP + cw],
                                    &W[(size_t)(n0 + r) * K + k0 + cw * 2], 16);
        }
    };

    load_stage(0, 0);
    __pipeline_commit();

    int cur = 0;
    for (int k0 = 0; k0 < K; k0 += 32) {
        if (k0 + 32 < K) {
            load_stage(cur ^ 1, k0 + 32);
            __pipeline_commit();
            __pipeline_wait_prior(1);
        } else {
            __pipeline_wait_prior(0);
        }
        __syncthreads();

#pragma unroll
        for (int ks = 0; ks < 2; ks++) {
            unsigned af[4][4], bf[4][2];
#pragma unroll
            for (int tm = 0; tm < 4; tm++) {
                int row = wm * 64 + tm * 16 + g;
                af[tm][0] = As[cur][row * HP + ks * 8 + t];
                af[tm][1] = As[cur][(row + 8) * HP + ks * 8 + t];
                af[tm][2] = As[cur][row * HP + ks * 8 + 4 + t];
                af[tm][3] = As[cur][(row + 8) * HP + ks * 8 + 4 + t];
            }
#pragma unroll
            for (int tn = 0; tn < 4; tn++) {
                int rowb = wn * 32 + tn * 8 + g;
                bf[tn][0] = Ws[cur][rowb * HP + ks * 8 + t];
                bf[tn][1] = Ws[cur][rowb * HP + ks * 8 + 4 + t];
            }
#pragma unroll
            for (int tm = 0; tm < 4; tm++)
#pragma unroll
                for (int tn = 0; tn < 4; tn++)
                    mma_bf16(c[tm][tn][0], c[tm][tn][1], c[tm][tn][2], c[tm][tn][3],
                             af[tm][0], af[tm][1], af[tm][2], af[tm][3],
                             bf[tn][0], bf[tn][1]);
        }
        __syncthreads();
        cur ^= 1;
    }

    float lsum = 0.f, lsq = 0.f;
#pragma unroll
    for (int tm = 0; tm < 4; tm++) {
        int row = m0 + wm * 64 + tm * 16 + g;
#pragma unroll
        for (int tn = 0; tn < 4; tn++) {
            int col = n0 + wn * 32 + tn * 8 + 2 * t;
            float2 x0 = *reinterpret_cast<const float2*>(&x[(size_t)row * N + col]);
            float2 x1 = *reinterpret_cast<const float2*>(&x[(size_t)(row + 8) * N + col]);
            float2 o0, o1;
            o0.x = c[tm][tn][0] + bias[col]     + x0.x;
            o0.y = c[tm][tn][1] + bias[col + 1] + x0.y;
            o1.x = c[tm][tn][2] + bias[col]     + x1.x;
            o1.y = c[tm][tn][3] + bias[col + 1] + x1.y;
            *reinterpret_cast<float2*>(&C[(size_t)row * N + col])       = o0;
            *reinterpret_cast<float2*>(&C[(size_t)(row + 8) * N + col]) = o1;
            lsum += o0.x + o0.y + o1.x + o1.y;
            lsq  += o0.x*o0.x + o0.y*o0.y + o1.x*o1.x + o1.y*o1.y;
        }
    }
#pragma unroll
    for (int off = 16; off > 0; off >>= 1) {
        lsum += __shfl_down_sync(0xffffffffu, lsum, off);
        lsq  += __shfl_down_sync(0xffffffffu, lsq,  off);
    }
    __shared__ float rs[8], rq[8];
    if (lane == 0) { rs[warpId] = lsum; rq[warpId] = lsq; }
    __syncthreads();
    if (tid == 0) {
        float s = 0.f, q = 0.f;
#pragma unroll
        for (int w = 0; w < 8; w++) { s += rs[w]; q += rq[w]; }
        int p = blockIdx.y * 8 + blockIdx.x;   // 0..511, 64 per batch
        g_psum[p] = s; g_psq[p] = q;
    }
}

// ---------------------------------------------------------------------------
// Repack: de-interleave qk/v. Q -> [b,h,s,64] row-major.
// K,V -> MMA-fragment-major 16KB tiles (tf32), as in R8.
// ---------------------------------------------------------------------------
__global__ void repack_kernel()
{
    __shared__ float sqk[2048 + 64];
    __shared__ float sv [1024 + 32];
    int bs = blockIdx.x;            // 0..8191
    int b = bs >> 10, s = bs & 1023;
    int tid = threadIdx.x;          // 256
    const float* qkrow = g_qk + (size_t)bs * NQK;
    const float* vrow  = g_v  + (size_t)bs * NV;
    for (int c = tid; c < 2048; c += 256) sqk[c + (c >> 5)] = qkrow[c];
    for (int c = tid; c < 1024; c += 256) sv [c + (c >> 5)] = vrow[c];
    __syncthreads();

    int jt = s >> 6, jl = s & 63;
    int kn  = jl >> 3, kg = jl & 7;
    int kn2 = kn >> 1, knp = kn & 1;
    int vt = jl & 3, vhi = (jl >> 2) & 1, vk = jl >> 3;

    for (int idx = tid; idx < 1024; idx += 256) {
        int h = idx >> 6, d = idx & 63;
        int cq = d * 32 + h;
        int ck = cq + 16;
        int cv = d * 16 + h;
        size_t bh = (size_t)(b * H_ + h);
        g_q[(bh * S_ + s) * 64 + d] = sqk[cq + (cq >> 5)];
        size_t tbase = (bh * 16 + jt) * 4096;
        {
            int k = d >> 3, t_ = d & 3, hi = (d >> 2) & 1;
            int lanek = kg * 4 + t_;
            int w = knp * 2 + hi;
            g_k[tbase + (size_t)(((k * 4 + kn2) * 32 + lanek) * 4 + w)] =
                rtf(sqk[ck + (ck >> 5)]);
        }
        {
            int n = d >> 3, gg = d & 7;
            int n2 = n >> 1, npar = n & 1;
            int lanev = gg * 4 + vt;
            int w = npar * 2 + vhi;
            g_vp[tbase + (size_t)(((vk * 4 + n2) * 32 + lanev) * 4 + w)] =
                rtf(sv[cv + (cv >> 5)]);
        }
    }
}

// ---------------------------------------------------------------------------
// TF32 tensor-core flash attention (unchanged from R8 except bf16 epilogue).
// ---------------------------------------------------------------------------
#define PA 68
#define TILE_W 4096                      // words per frag-major K or V tile
#define AT_SMEM_BYTES ((128 * PA + 4 * TILE_W) * 4)   // Q/P + 2xK + 2xV

__global__ __launch_bounds__(256, 2)
void attn_tc_kernel()
{
    extern __shared__ unsigned smu[];
    unsigned* Qs = smu;                            // [128][PA]; becomes Ps
    unsigned* Ks = smu + 128 * PA;                 // [2][4096]
    unsigned* Vs = smu + 128 * PA + 2 * TILE_W;    // [2][4096]

    int tid  = threadIdx.x;
    int warp = tid >> 5, lane = tid & 31;
    int g = lane >> 2, t = lane & 3;
    int i0 = blockIdx.x * 128;
    int h  = blockIdx.y, b = blockIdx.z;
    int bh = b * H_ + h;
    const float* Qb = g_q  + ((size_t)bh * S_ + i0) * KD_;
    const float* Kb = g_k  + (size_t)bh * 16 * TILE_W;
    const float* Vb = g_vp + (size_t)bh * 16 * TILE_W;
    const float QSCL = 0.125f * 1.4426950408889634f;  // 1/sqrt(64) * log2(e)

    auto load_kv = [&](int st, int jt) {
        const float* Kt = Kb + (size_t)jt * TILE_W;
        const float* Vt = Vb + (size_t)jt * TILE_W;
#pragma unroll
        for (int l = 0; l < 4; l++) {
            int idx = tid + l * 256;
            __pipeline_memcpy_async(&Ks[st * TILE_W + idx * 4], &Kt[idx * 4], 16);
            __pipeline_memcpy_async(&Vs[st * TILE_W + idx * 4], &Vt[idx * 4], 16);
        }
    };

    load_kv(0, 0);
    __pipeline_commit();

    for (int idx = tid; idx < 128 * 16; idx += 256) {
        int r = idx >> 4, c4 = (idx & 15) * 4;
        float4 q = *reinterpret_cast<const float4*>(&Qb[(size_t)r * 64 + c4]);
        Qs[r * PA + c4 + 0] = f2tf32(q.x * QSCL);
        Qs[r * PA + c4 + 1] = f2tf32(q.y * QSCL);
        Qs[r * PA + c4 + 2] = f2tf32(q.z * QSCL);
        Qs[r * PA + c4 + 3] = f2tf32(q.w * QSCL);
    }
    __syncthreads();

    int wr = warp * 16;
    unsigned qf[8][4];
#pragma unroll
    for (int k = 0; k < 8; k++) {
        qf[k][0] = Qs[(wr + g)     * PA + k * 8 + t];
        qf[k][1] = Qs[(wr + g + 8) * PA + k * 8 + t];
        qf[k][2] = Qs[(wr + g)     * PA + k * 8 + 4 + t];
        qf[k][3] = Qs[(wr + g + 8) * PA + k * 8 + 4 + t];
    }
    __syncthreads();
    unsigned* Ps = Qs;

    float accO[8][4];
#pragma unroll
    for (int n = 0; n < 8; n++)
#pragma unroll
        for (int f = 0; f < 4; f++) accO[n][f] = 0.f;
    float m0 = -1e30f, m1 = -1e30f, l0 = 0.f, l1 = 0.f;

    int cur = 0;
    for (int jt = 0; jt < 16; jt++) {
        if (jt + 1 < 16) {
            load_kv(cur ^ 1, jt + 1);
            __pipeline_commit();
            __pipeline_wait_prior(1);
        } else {
            __pipeline_wait_prior(0);
        }
        __syncthreads();
        const uint4* K4 = reinterpret_cast<const uint4*>(Ks + cur * TILE_W);
        const uint4* V4 = reinterpret_cast<const uint4*>(Vs + cur * TILE_W);

        float sacc[8][4];
#pragma unroll
        for (int n = 0; n < 8; n++)
#pragma unroll
            for (int f = 0; f < 4; f++) sacc[n][f] = 0.f;
#pragma unroll
        for (int k = 0; k < 8; k++) {
#pragma unroll
            for (int n2 = 0; n2 < 4; n2++) {
                uint4 bb = K4[(k * 4 + n2) * 32 + lane];
                mma_tf32(sacc[2*n2][0], sacc[2*n2][1], sacc[2*n2][2], sacc[2*n2][3],
                         qf[k][0], qf[k][1], qf[k][2], qf[k][3], bb.x, bb.y);
                mma_tf32(sacc[2*n2+1][0], sacc[2*n2+1][1], sacc[2*n2+1][2], sacc[2*n2+1][3],
                         qf[k][0], qf[k][1], qf[k][2], qf[k][3], bb.z, bb.w);
            }
        }

        float tm0 = -1e30f, tm1 = -1e30f;
#pragma unroll
        for (int n = 0; n < 8; n++) {
            tm0 = fmaxf(tm0, fmaxf(sacc[n][0], sacc[n][1]));
            tm1 = fmaxf(tm1, fmaxf(sacc[n][2], sacc[n][3]));
        }
        tm0 = fmaxf(tm0, __shfl_xor_sync(0xffffffffu, tm0, 1));
        tm0 = fmaxf(tm0, __shfl_xor_sync(0xffffffffu, tm0, 2));
        tm1 = fmaxf(tm1, __shfl_xor_sync(0xffffffffu, tm1, 1));
        tm1 = fmaxf(tm1, __shfl_xor_sync(0xffffffffu, tm1, 2));
        float mn0 = fmaxf(m0, tm0), mn1 = fmaxf(m1, tm1);
        float sc0 = fexp2(m0 - mn0), sc1 = fexp2(m1 - mn1);
        float ps0 = 0.f, ps1 = 0.f;
#pragma unroll
        for (int n = 0; n < 8; n++) {
            float p0 = fexp2(sacc[n][0] - mn0);
            float p1 = fexp2(sacc[n][1] - mn0);
            float p2 = fexp2(sacc[n][2] - mn1);
            float p3 = fexp2(sacc[n][3] - mn1);
            ps0 += p0 + p1; ps1 += p2 + p3;
            *reinterpret_cast<uint2*>(&Ps[(wr + g)     * PA + n * 8 + 2 * t]) =
                make_uint2(f2tf32(p0), f2tf32(p1));
            *reinterpret_cast<uint2*>(&Ps[(wr + g + 8) * PA + n * 8 + 2 * t]) =
                make_uint2(f2tf32(p2), f2tf32(p3));
            accO[n][0] *= sc0; accO[n][1] *= sc0;
            accO[n][2] *= sc1; accO[n][3] *= sc1;
        }
        ps0 += __shfl_xor_sync(0xffffffffu, ps0, 1);
        ps0 += __shfl_xor_sync(0xffffffffu, ps0, 2);
        ps1 += __shfl_xor_sync(0xffffffffu, ps1, 1);
        ps1 += __shfl_xor_sync(0xffffffffu, ps1, 2);
        l0 = l0 * sc0 + ps0;
        l1 = l1 * sc1 + ps1;
        m0 = mn0; m1 = mn1;
        __syncwarp();

#pragma unroll
        for (int k = 0; k < 8; k++) {
            unsigned a0 = Ps[(wr + g)     * PA + k * 8 + t];
            unsigned a1 = Ps[(wr + g + 8) * PA + k * 8 + t];
            unsigned a2 = Ps[(wr + g)     * PA + k * 8 + 4 + t];
            unsigned a3 = Ps[(wr + g + 8) * PA + k * 8 + 4 + t];
#pragma unroll
            for (int n2 = 0; n2 < 4; n2++) {
                uint4 bb = V4[(k * 4 + n2) * 32 + lane];
                mma_tf32(accO[2*n2][0], accO[2*n2][1], accO[2*n2][2], accO[2*n2][3],
                         a0, a1, a2, a3, bb.x, bb.y);
                mma_tf32(accO[2*n2+1][0], accO[2*n2+1][1], accO[2*n2+1][2], accO[2*n2+1][3],
                         a0, a1, a2, a3, bb.z, bb.w);
            }
        }
        __syncthreads();
        cur ^= 1;
    }

    // epilogue: normalize, write bf16 (oproj raw-copies it)
    float inv0 = 1.f / l0, inv1 = 1.f / l1;
    int row0 = i0 + wr + g, row1 = row0 + 8;
#pragma unroll
    for (int n = 0; n < 8; n++) {
        int col = h * 64 + n * 8 + 2 * t;
        __nv_bfloat162 o0 = __floats2bfloat162_rn(accO[n][0] * inv0, accO[n][1] * inv0);
        __nv_bfloat162 o1 = __floats2bfloat162_rn(accO[n][2] * inv1, accO[n][3] * inv1);
        *reinterpret_cast<unsigned*>(&g_aoh[(size_t)(b * S_ + row0) * NV + col]) =
            *reinterpret_cast<unsigned*>(&o0);
        *reinterpret_cast<unsigned*>(&g_aoh[(size_t)(b * S_ + row1) * NV + col]) =
            *reinterpret_cast<unsigned*>(&o1);
    }
}

// ---------------------------------------------------------------------------
// LN stats reduce + finalize
// ---------------------------------------------------------------------------
__global__ void stats_reduce()
{
    int w = threadIdx.x >> 5, lane = threadIdx.x & 31;
    float s = g_psum[w * 64 + lane] + g_psum[w * 64 + 32 + lane];
    float q = g_psq [w * 64 + lane] + g_psq [w * 64 + 32 + lane];
#pragma unroll
    for (int off = 16; off > 0; off >>= 1) {
        s += __shfl_down_sync(0xffffffffu, s, off);
        q += __shfl_down_sync(0xffffffffu, q, off);
    }
    if (lane == 0) { g_stats[2 * w] = s; g_stats[2 * w + 1] = q; }
}

__global__ void ln_finalize(float* __restrict__ y,
                            const float* __restrict__ lnw,
                            const float* __restrict__ lnb)
{
    int idx = blockIdx.x * 256 + threadIdx.x;
    int b   = idx >> 18;
    int sd4 = idx & ((1 << 18) - 1);
    const float invn = 1.0f / 1048576.0f;
    float mean = g_stats[2 * b] * invn;
    float var  = g_stats[2 * b + 1] * invn - mean * mean;
    float inv  = rsqrtf(var + 1e-5f);
    float4 v  = reinterpret_cast<float4*>(y)[idx];
    float4 w  = reinterpret_cast<const float4*>(lnw)[sd4];
    float4 bb = reinterpret_cast<const float4*>(lnb)[sd4];
    v.x = (v.x - mean) * inv * w.x + bb.x;
    v.y = (v.y - mean) * inv * w.y + bb.y;
    v.z = (v.z - mean) * inv * w.z + bb.z;
    v.w = (v.w - mean) * inv * w.w + bb.w;
    reinterpret_cast<float4*>(y)[idx] = v;
}

// ---------------------------------------------------------------------------
// kernel_launch
// ---------------------------------------------------------------------------
extern "C" void kernel_launch(void* const* d_in, const int* in_sizes, int n_in,
                              void* d_out, int out_size)
{
    const float* x    = (const float*)d_in[0];
    const float* W_qk = (const float*)d_in[1];
    const float* b_qk = (const float*)d_in[2];
    const float* W_v  = (const float*)d_in[3];
    const float* b_v  = (const float*)d_in[4];
    const float* W_o  = (const float*)d_in[5];
    const float* b_o  = (const float*)d_in[6];
    const float* ln_w = (const float*)d_in[7];
    const float* ln_b = (const float*)d_in[8];
    float* out = (float*)d_out;

    void *p_qk, *p_v, *p_aoh, *p_xh, *p_wqkh, *p_wvh, *p_woh;
    cudaGetSymbolAddress(&p_qk,   g_qk);
    cudaGetSymbolAddress(&p_v,    g_v);
    cudaGetSymbolAddress(&p_aoh,  g_aoh);
    cudaGetSymbolAddress(&p_xh,   g_xh);
    cudaGetSymbolAddress(&p_wqkh, g_wqkh);
    cudaGetSymbolAddress(&p_wvh,  g_wvh);
    cudaGetSymbolAddress(&p_woh,  g_woh);

    cudaFuncSetAttribute(attn_tc_kernel, cudaFuncAttributeMaxDynamicSharedMemorySize,
                         AT_SMEM_BYTES);

    // 0) bf16 packing of x + weights
    pack_bf16_kernel<<<(B_*S_*D_) / 1024, 256>>>((__nv_bfloat16*)p_xh,   x);
    pack_bf16_kernel<<<(NQK*D_)   / 1024, 256>>>((__nv_bfloat16*)p_wqkh, W_qk);
    pack_bf16_kernel<<<(NV*D_)    / 1024, 256>>>((__nv_bfloat16*)p_wvh,  W_v);
    pack_bf16_kernel<<<(D_*NV)    / 1024, 256>>>((__nv_bfloat16*)p_woh,  W_o);

    // 1) qk = x @ W_qk^T + b_qk   (8192 x 2048) — bf16 MMA
    hgemm_bias<<<dim3(NQK / 128, MROWS / 128), 256>>>((const __nv_bfloat16*)p_xh,
                                                      (const __nv_bfloat16*)p_wqkh, b_qk,
                                                      (float*)p_qk, NQK);
    // 2) v  = x @ W_v^T + b_v     (8192 x 1024) — bf16 MMA
    hgemm_bias<<<dim3(NV / 128, MROWS / 128), 256>>>((const __nv_bfloat16*)p_xh,
                                                     (const __nv_bfloat16*)p_wvh, b_v,
                                                     (float*)p_v, NV);
    // 3) repack: Q row-major; K/V frag-major tiles (tf32)
    repack_kernel<<<MROWS, 256>>>();
    // 4) flash attention — TF32 MMA, frag-major K/V, cp.async pipeline
    attn_tc_kernel<<<dim3(S_ / 128, H_, B_), 256, AT_SMEM_BYTES>>>();
    // 5) O-proj (bf16 MMA) + bias + residual + partial LN stats
    hgemm_oproj<<<dim3(NV / 128, MROWS / 128), 256>>>((const __nv_bfloat16*)p_aoh,
                                                      (const __nv_bfloat16*)p_woh, b_o, x, out);
    // 6) reduce stats per batch
    stats_reduce<<<1, 256>>>();
    // 7) LayerNorm finalize
    ln_finalize<<<(B_ * S_ * D_ / 4) / 256, 256>>>(out, ln_w, ln_b);
}

// round 11
// speedup vs baseline: 2.1946x; 1.2569x over previous
#include <cuda_runtime.h>
#include <cuda_pipeline.h>
#include <cuda_bf16.h>
#include <math.h>

// Problem constants
#define B_   8
#define S_   1024
#define D_   1024
#define H_   16
#define KD_  64
#define VD_  64
#define NQK  2048          // H*KD*2
#define NV   1024          // H*VD
#define MROWS (B_*S_)      // 8192

// ---------------------------------------------------------------------------
// Scratch (static device arrays — no runtime allocation)
// ---------------------------------------------------------------------------
__device__ float g_qk [B_*S_*NQK];          // x @ W_qk^T + b   (f32)
__device__ float g_v  [B_*S_*NV];           // x @ W_v^T  + b   (f32)
__device__ __nv_bfloat16 g_qh[B_*H_*S_*KD_]; // Q bf16 [bh,s,kd], pre-scaled
__device__ __nv_bfloat16 g_kh[B_*H_*S_*KD_]; // K bf16 frag-major 8KB tiles
__device__ __nv_bfloat16 g_vh[B_*H_*S_*VD_]; // V bf16 frag-major 8KB tiles
__device__ __nv_bfloat16 g_aoh[B_*S_*NV];   // attention out (bf16)
__device__ __nv_bfloat16 g_xh [B_*S_*D_];   // bf16 x
__device__ __nv_bfloat16 g_wqkh[NQK*D_];    // bf16 W_qk
__device__ __nv_bfloat16 g_wvh [NV*D_];     // bf16 W_v
__device__ __nv_bfloat16 g_woh [D_*NV];     // bf16 W_o
__device__ float g_psum[512];
__device__ float g_psq [512];
__device__ float g_stats[16];               // per-batch {sum, sumsq}

// ---------------------------------------------------------------------------
// MMA helpers
// ---------------------------------------------------------------------------
// bf16 m16n8k16: a0=A[g][2t,2t+1], a1=A[g+8][2t,2t+1], a2=A[g][2t+8,2t+9],
// a3=A[g+8][2t+8,2t+9]; b0={B[2t][g],B[2t+1][g]}, b1={B[2t+8][g],B[2t+9][g]}.
__device__ __forceinline__ void mma_bf16(float& c0, float& c1, float& c2, float& c3,
                                         unsigned a0, unsigned a1, unsigned a2, unsigned a3,
                                         unsigned b0, unsigned b1) {
    asm volatile(
        "mma.sync.aligned.m16n8k16.row.col.f32.bf16.bf16.f32 "
        "{%0,%1,%2,%3}, {%4,%5,%6,%7}, {%8,%9}, {%0,%1,%2,%3};"
        : "+f"(c0), "+f"(c1), "+f"(c2), "+f"(c3)
        : "r"(a0), "r"(a1), "r"(a2), "r"(a3), "r"(b0), "r"(b1));
}

// FMA-pipe exp2 (no MUFU): deg-6 poly + exponent-field add
__device__ __forceinline__ float fexp2(float y) {
    y = fmaxf(y, -80.f);
    float tt = y + 12582912.f;                 // 1.5*2^23: round-to-nearest
    float f  = y - (tt - 12582912.f);          // f in [-0.5, 0.5]
    float p  = 1.5403530393381610e-4f;
    p = p * f + 1.3333558146428443e-3f;
    p = p * f + 9.6181291076284770e-3f;
    p = p * f + 5.5504108664821580e-2f;
    p = p * f + 2.4022650695910071e-1f;
    p = p * f + 6.9314718055994531e-1f;
    p = p * f + 1.0f;
    return __int_as_float(__float_as_int(p) + (__float_as_int(tt) << 23));
}

__device__ __forceinline__ unsigned packbf(float a, float b) {
    __nv_bfloat162 p = __floats2bfloat162_rn(a, b);
    return *reinterpret_cast<unsigned*>(&p);
}

// ---------------------------------------------------------------------------
// bf16 packing pass (rn rounding; cp.async then copies raw bf16)
// ---------------------------------------------------------------------------
__global__ void pack_bf16_kernel(__nv_bfloat16* __restrict__ dst,
                                 const float* __restrict__ src)
{
    int i = blockIdx.x * 256 + threadIdx.x;
    float4 v = reinterpret_cast<const float4*>(src)[i];
    uint2 o;
    o.x = packbf(v.x, v.y);
    o.y = packbf(v.z, v.w);
    reinterpret_cast<uint2*>(dst)[i] = o;
}

// ---------------------------------------------------------------------------
// bf16 tensor-core GEMM, cp.async 2-stage pipeline (unchanged from R9).
// ---------------------------------------------------------------------------
#define HP 20   // smem pitch in 32-bit words

__global__ __launch_bounds__(256, 2)
void hgemm_bias(const __nv_bfloat16* __restrict__ A, const __nv_bfloat16* __restrict__ W,
                const float* __restrict__ bias, float* __restrict__ C, int N)
{
    __shared__ unsigned As[2][128 * HP];
    __shared__ unsigned Ws[2][128 * HP];
    const int K = 1024;
    int tid = threadIdx.x;
    int warpId = tid >> 5, lane = tid & 31;
    int wm = warpId >> 2, wn = warpId & 3;
    int g = lane >> 2, t = lane & 3;
    int m0 = blockIdx.y * 128, n0 = blockIdx.x * 128;

    float c[4][4][4];
#pragma unroll
    for (int i = 0; i < 4; i++)
#pragma unroll
        for (int j = 0; j < 4; j++)
#pragma unroll
            for (int f = 0; f < 4; f++) c[i][j][f] = 0.f;

    auto load_stage = [&](int st, int k0) {
#pragma unroll
        for (int l = 0; l < 2; l++) {
            int idx = tid + l * 256;            // 0..511
            int r   = idx >> 2;                 // 0..127
            int cw  = (idx & 3) * 4;            // word offset 0,4,8,12
            __pipeline_memcpy_async(&As[st][r * HP + cw],
                                    &A[(size_t)(m0 + r) * K + k0 + cw * 2], 16);
            __pipeline_memcpy_async(&Ws[st][r * HP + cw],
                                    &W[(size_t)(n0 + r) * K + k0 + cw * 2], 16);
        }
    };

    load_stage(0, 0);
    __pipeline_commit();

    int cur = 0;
    for (int k0 = 0; k0 < K; k0 += 32) {
        if (k0 + 32 < K) {
            load_stage(cur ^ 1, k0 + 32);
            __pipeline_commit();
            __pipeline_wait_prior(1);
        } else {
            __pipeline_wait_prior(0);
        }
        __syncthreads();

#pragma unroll
        for (int ks = 0; ks < 2; ks++) {
            unsigned af[4][4], bf[4][2];
#pragma unroll
            for (int tm = 0; tm < 4; tm++) {
                int row = wm * 64 + tm * 16 + g;
                af[tm][0] = As[cur][row * HP + ks * 8 + t];
                af[tm][1] = As[cur][(row + 8) * HP + ks * 8 + t];
                af[tm][2] = As[cur][row * HP + ks * 8 + 4 + t];
                af[tm][3] = As[cur][(row + 8) * HP + ks * 8 + 4 + t];
            }
#pragma unroll
            for (int tn = 0; tn < 4; tn++) {
                int rowb = wn * 32 + tn * 8 + g;
                bf[tn][0] = Ws[cur][rowb * HP + ks * 8 + t];
                bf[tn][1] = Ws[cur][rowb * HP + ks * 8 + 4 + t];
            }
#pragma unroll
            for (int tm = 0; tm < 4; tm++)
#pragma unroll
                for (int tn = 0; tn < 4; tn++)
                    mma_bf16(c[tm][tn][0], c[tm][tn][1], c[tm][tn][2], c[tm][tn][3],
                             af[tm][0], af[tm][1], af[tm][2], af[tm][3],
                             bf[tn][0], bf[tn][1]);
        }
        __syncthreads();
        cur ^= 1;
    }

#pragma unroll
    for (int tm = 0; tm < 4; tm++) {
        int row = m0 + wm * 64 + tm * 16 + g;
#pragma unroll
        for (int tn = 0; tn < 4; tn++) {
            int col = n0 + wn * 32 + tn * 8 + 2 * t;
            float2 o0, o1;
            o0.x = c[tm][tn][0] + bias[col];
            o0.y = c[tm][tn][1] + bias[col + 1];
            o1.x = c[tm][tn][2] + bias[col];
            o1.y = c[tm][tn][3] + bias[col + 1];
            *reinterpret_cast<float2*>(&C[(size_t)row * N + col])       = o0;
            *reinterpret_cast<float2*>(&C[(size_t)(row + 8) * N + col]) = o1;
        }
    }
}

// ---------------------------------------------------------------------------
// O-projection (bf16 MMA): C = A @ W_o^T + b_o + x, + LN partials
// ---------------------------------------------------------------------------
__global__ __launch_bounds__(256, 2)
void hgemm_oproj(const __nv_bfloat16* __restrict__ A, const __nv_bfloat16* __restrict__ W,
                 const float* __restrict__ bias, const float* __restrict__ x,
                 float* __restrict__ C)
{
    __shared__ unsigned As[2][128 * HP];
    __shared__ unsigned Ws[2][128 * HP];
    const int K = 1024, N = 1024;
    int tid = threadIdx.x;
    int warpId = tid >> 5, lane = tid & 31;
    int wm = warpId >> 2, wn = warpId & 3;
    int g = lane >> 2, t = lane & 3;
    int m0 = blockIdx.y * 128, n0 = blockIdx.x * 128;

    float c[4][4][4];
#pragma unroll
    for (int i = 0; i < 4; i++)
#pragma unroll
        for (int j = 0; j < 4; j++)
#pragma unroll
            for (int f = 0; f < 4; f++) c[i][j][f] = 0.f;

    auto load_stage = [&](int st, int k0) {
#pragma unroll
        for (int l = 0; l < 2; l++) {
            int idx = tid + l * 256;
            int r   = idx >> 2;
            int cw  = (idx & 3) * 4;
            __pipeline_memcpy_async(&As[st][r * HP + cw],
                                    &A[(size_t)(m0 + r) * K + k0 + cw * 2], 16);
            __pipeline_memcpy_async(&Ws[st][r * HP + cw],
                                    &W[(size_t)(n0 + r) * K + k0 + cw * 2], 16);
        }
    };

    load_stage(0, 0);
    __pipeline_commit();

    int cur = 0;
    for (int k0 = 0; k0 < K; k0 += 32) {
        if (k0 + 32 < K) {
            load_stage(cur ^ 1, k0 + 32);
            __pipeline_commit();
            __pipeline_wait_prior(1);
        } else {
            __pipeline_wait_prior(0);
        }
        __syncthreads();

#pragma unroll
        for (int ks = 0; ks < 2; ks++) {
            unsigned af[4][4], bf[4][2];
#pragma unroll
            for (int tm = 0; tm < 4; tm++) {
                int row = wm * 64 + tm * 16 + g;
                af[tm][0] = As[cur][row * HP + ks * 8 + t];
                af[tm][1] = As[cur][(row + 8) * HP + ks * 8 + t];
                af[tm][2] = As[cur][row * HP + ks * 8 + 4 + t];
                af[tm][3] = As[cur][(row + 8) * HP + ks * 8 + 4 + t];
            }
#pragma unroll
            for (int tn = 0; tn < 4; tn++) {
                int rowb = wn * 32 + tn * 8 + g;
                bf[tn][0] = Ws[cur][rowb * HP + ks * 8 + t];
                bf[tn][1] = Ws[cur][rowb * HP + ks * 8 + 4 + t];
            }
#pragma unroll
            for (int tm = 0; tm < 4; tm++)
#pragma unroll
                for (int tn = 0; tn < 4; tn++)
                    mma_bf16(c[tm][tn][0], c[tm][tn][1], c[tm][tn][2], c[tm][tn][3],
                             af[tm][0], af[tm][1], af[tm][2], af[tm][3],
                             bf[tn][0], bf[tn][1]);
        }
        __syncthreads();
        cur ^= 1;
    }

    float lsum = 0.f, lsq = 0.f;
#pragma unroll
    for (int tm = 0; tm < 4; tm++) {
        int row = m0 + wm * 64 + tm * 16 + g;
#pragma unroll
        for (int tn = 0; tn < 4; tn++) {
            int col = n0 + wn * 32 + tn * 8 + 2 * t;
            float2 x0 = *reinterpret_cast<const float2*>(&x[(size_t)row * N + col]);
            float2 x1 = *reinterpret_cast<const float2*>(&x[(size_t)(row + 8) * N + col]);
            float2 o0, o1;
            o0.x = c[tm][tn][0] + bias[col]     + x0.x;
            o0.y = c[tm][tn][1] + bias[col + 1] + x0.y;
            o1.x = c[tm][tn][2] + bias[col]     + x1.x;
            o1.y = c[tm][tn][3] + bias[col + 1] + x1.y;
            *reinterpret_cast<float2*>(&C[(size_t)row * N + col])       = o0;
            *reinterpret_cast<float2*>(&C[(size_t)(row + 8) * N + col]) = o1;
            lsum += o0.x + o0.y + o1.x + o1.y;
            lsq  += o0.x*o0.x + o0.y*o0.y + o1.x*o1.x + o1.y*o1.y;
        }
    }
#pragma unroll
    for (int off = 16; off > 0; off >>= 1) {
        lsum += __shfl_down_sync(0xffffffffu, lsum, off);
        lsq  += __shfl_down_sync(0xffffffffu, lsq,  off);
    }
    __shared__ float rs[8], rq[8];
    if (lane == 0) { rs[warpId] = lsum; rq[warpId] = lsq; }
    __syncthreads();
    if (tid == 0) {
        float s = 0.f, q = 0.f;
#pragma unroll
        for (int w = 0; w < 8; w++) { s += rs[w]; q += rq[w]; }
        int p = blockIdx.y * 8 + blockIdx.x;   // 0..511, 64 per batch
        g_psum[p] = s; g_psq[p] = q;
    }
}

// ---------------------------------------------------------------------------
// Repack: de-interleave qk/v into bf16.
//   Q -> [bh,s,kd] bf16, pre-scaled by QSCL (kd pairs packed per word)
//   K -> frag-major 8KB tiles: word ((k*4+n2)*32 + g*4+t)*4 + npar*2+bh,
//        packing K[j][16k+8bh+2t .. +1]; n-side from j: n2=jl>>4,npar,g=jl&7
//   V -> frag-major 8KB tiles: word packs {V[j][vd], V[j+1][vd]} with
//        j=16k+8jh+2t; n-side from vd.
// Block handles TWO s-rows so V's (j,j+1) pairs pack into single words.
// ---------------------------------------------------------------------------
#define QSCL_ (0.125f * 1.4426950408889634f)   // 1/sqrt(64) * log2(e)

__global__ void repack_kernel()
{
    __shared__ float sqk[2][2048 + 64];
    __shared__ float sv [2][1024 + 32];
    int sp = blockIdx.x;              // 0..4095
    int b  = sp >> 9;
    int s0 = (sp & 511) * 2;
    int tid = threadIdx.x;            // 256
    const float* qk0 = g_qk + ((size_t)(b * S_) + s0) * NQK;
    const float* v0  = g_v  + ((size_t)(b * S_) + s0) * NV;
#pragma unroll
    for (int r = 0; r < 2; r++) {
        for (int c = tid; c < 2048; c += 256) sqk[r][c + (c >> 5)] = qk0[(size_t)r * NQK + c];
        for (int c = tid; c < 1024; c += 256) sv [r][c + (c >> 5)] = v0 [(size_t)r * NV  + c];
    }
    __syncthreads();

    int jt  = s0 >> 6;
    int jl0 = s0 & 63;
    unsigned* qh = reinterpret_cast<unsigned*>(g_qh);
    unsigned* kh = reinterpret_cast<unsigned*>(g_kh);
    unsigned* vh = reinterpret_cast<unsigned*>(g_vh);

    // Q + K: (r, h, kd2) -> 2*16*32 = 1024 words each
    for (int idx = tid; idx < 1024; idx += 256) {
        int r = idx >> 9, rem = idx & 511;
        int h = rem >> 5, kd2 = rem & 31;
        int s = s0 + r, jl = jl0 + r;
        size_t bh = (size_t)(b * H_ + h);
        int cq0 = (2 * kd2) * 32 + h, cq1 = cq0 + 32;
        float q0 = sqk[r][cq0 + (cq0 >> 5)];
        float q1 = sqk[r][cq1 + (cq1 >> 5)];
        qh[(bh * S_ + s) * 32 + kd2] = packbf(q0 * QSCL_, q1 * QSCL_);
        int ck0 = cq0 + 16, ck1 = cq1 + 16;
        float k0 = sqk[r][ck0 + (ck0 >> 5)];
        float k1 = sqk[r][ck1 + (ck1 >> 5)];
        int kk = kd2 >> 3, bhf = (kd2 >> 2) & 1, t = kd2 & 3;
        int n2 = jl >> 4, npar = (jl >> 3) & 1, g = jl & 7;
        kh[(bh * 16 + jt) * 2048 +
           (size_t)(((kk * 4 + n2) * 32 + g * 4 + t) * 4 + npar * 2 + bhf)] =
            packbf(k0, k1);
    }

    // V: (h, vd) -> 1024 words, each packs rows (s0, s0+1)
    {
        int kk = jl0 >> 4, jh = (jl0 >> 3) & 1, t = (jl0 & 7) >> 1;
        for (int idx = tid; idx < 1024; idx += 256) {
            int h = idx >> 6, vd = idx & 63;
            int cv = vd * 16 + h;
            float va = sv[0][cv + (cv >> 5)];
            float vb = sv[1][cv + (cv >> 5)];
            int n2 = vd >> 4, npar = (vd >> 3) & 1, g = vd & 7;
            vh[((size_t)(b * H_ + h) * 16 + jt) * 2048 +
               (size_t)(((kk * 4 + n2) * 32 + g * 4 + t) * 4 + npar * 2 + jh)] =
                packbf(va, vb);
        }
    }
}

// ---------------------------------------------------------------------------
// bf16 tensor-core flash attention; register-resident P (S c-frag == P a-frag
// for m16n8k16); K/V frag-major 8KB tiles via cp.async 2-stage pipeline.
// CTA = (b, h, 128 q-rows); 8 warps, warp owns 16 rows; j-tiles of 64.
// ---------------------------------------------------------------------------
#define TILE_HW 2048                    // words per bf16 frag tile
#define AT_SMEM_BYTES (4 * TILE_HW * 4) // 2xK + 2xV = 32KB

__global__ __launch_bounds__(256, 2)
void attn_tc_kernel()
{
    extern __shared__ unsigned smu[];
    unsigned* Ks = smu;                  // [2][2048]
    unsigned* Vs = smu + 2 * TILE_HW;    // [2][2048]

    int tid  = threadIdx.x;
    int warp = tid >> 5, lane = tid & 31;
    int g = lane >> 2, t = lane & 3;
    int i0 = blockIdx.x * 128;
    int h  = blockIdx.y, b = blockIdx.z;
    int bh = b * H_ + h;
    const unsigned* Qw = reinterpret_cast<const unsigned*>(g_qh) +
                         ((size_t)bh * S_ + i0) * 32;
    const unsigned* Kb = reinterpret_cast<const unsigned*>(g_kh) + (size_t)bh * 16 * TILE_HW;
    const unsigned* Vb = reinterpret_cast<const unsigned*>(g_vh) + (size_t)bh * 16 * TILE_HW;

    auto load_kv = [&](int st, int jt) {
        const unsigned* Kt = Kb + (size_t)jt * TILE_HW;
        const unsigned* Vt = Vb + (size_t)jt * TILE_HW;
#pragma unroll
        for (int l = 0; l < 2; l++) {
            int idx = tid + l * 256;        // 0..511
            __pipeline_memcpy_async(&Ks[st * TILE_HW + idx * 4], &Kt[idx * 4], 16);
            __pipeline_memcpy_async(&Vs[st * TILE_HW + idx * 4], &Vt[idx * 4], 16);
        }
    };

    load_kv(0, 0);
    __pipeline_commit();

    // Q a-frags straight from gmem (bf16 words, pre-scaled)
    int wr = warp * 16;
    unsigned qf[4][4];
#pragma unroll
    for (int k = 0; k < 4; k++) {
        qf[k][0] = Qw[(wr + g)     * 32 + k * 8 + t];
        qf[k][1] = Qw[(wr + g + 8) * 32 + k * 8 + t];
        qf[k][2] = Qw[(wr + g)     * 32 + k * 8 + 4 + t];
        qf[k][3] = Qw[(wr + g + 8) * 32 + k * 8 + 4 + t];
    }

    float accO[8][4];
#pragma unroll
    for (int n = 0; n < 8; n++)
#pragma unroll
        for (int f = 0; f < 4; f++) accO[n][f] = 0.f;
    float m0 = -1e30f, m1 = -1e30f, l0 = 0.f, l1 = 0.f;

    int cur = 0;
    for (int jt = 0; jt < 16; jt++) {
        if (jt + 1 < 16) {
            load_kv(cur ^ 1, jt + 1);
            __pipeline_commit();
            __pipeline_wait_prior(1);
        } else {
            __pipeline_wait_prior(0);
        }
        __syncthreads();
        const uint4* K4 = reinterpret_cast<const uint4*>(Ks + cur * TILE_HW);
        const uint4* V4 = reinterpret_cast<const uint4*>(Vs + cur * TILE_HW);

        // S = Q K^T  (warp: 16 x 64), 4 k16-steps, one LDS.128 per (k,n2)
        float sacc[8][4];
#pragma unroll
        for (int n = 0; n < 8; n++)
#pragma unroll
            for (int f = 0; f < 4; f++) sacc[n][f] = 0.f;
#pragma unroll
        for (int k = 0; k < 4; k++) {
#pragma unroll
            for (int n2 = 0; n2 < 4; n2++) {
                uint4 bb = K4[(k * 4 + n2) * 32 + lane];
                mma_bf16(sacc[2*n2][0], sacc[2*n2][1], sacc[2*n2][2], sacc[2*n2][3],
                         qf[k][0], qf[k][1], qf[k][2], qf[k][3], bb.x, bb.y);
                mma_bf16(sacc[2*n2+1][0], sacc[2*n2+1][1], sacc[2*n2+1][2], sacc[2*n2+1][3],
                         qf[k][0], qf[k][1], qf[k][2], qf[k][3], bb.z, bb.w);
            }
        }

        // online softmax (rows wr+g, wr+g+8), exp2 on FMA pipe
        float tm0 = -1e30f, tm1 = -1e30f;
#pragma unroll
        for (int n = 0; n < 8; n++) {
            tm0 = fmaxf(tm0, fmaxf(sacc[n][0], sacc[n][1]));
            tm1 = fmaxf(tm1, fmaxf(sacc[n][2], sacc[n][3]));
        }
        tm0 = fmaxf(tm0, __shfl_xor_sync(0xffffffffu, tm0, 1));
        tm0 = fmaxf(tm0, __shfl_xor_sync(0xffffffffu, tm0, 2));
        tm1 = fmaxf(tm1, __shfl_xor_sync(0xffffffffu, tm1, 1));
        tm1 = fmaxf(tm1, __shfl_xor_sync(0xffffffffu, tm1, 2));
        float mn0 = fmaxf(m0, tm0), mn1 = fmaxf(m1, tm1);
        float sc0 = fexp2(m0 - mn0), sc1 = fexp2(m1 - mn1);
        float ps0 = 0.f, ps1 = 0.f;
        unsigned pp0[8], pp1[8];       // P a-frag words, register-resident
#pragma unroll
        for (int n = 0; n < 8; n++) {
            float p0 = fexp2(sacc[n][0] - mn0);
            float p1 = fexp2(sacc[n][1] - mn0);
            float p2 = fexp2(sacc[n][2] - mn1);
            float p3 = fexp2(sacc[n][3] - mn1);
            ps0 += p0 + p1; ps1 += p2 + p3;
            pp0[n] = packbf(p0, p1);   // row g
            pp1[n] = packbf(p2, p3);   // row g+8
            accO[n][0] *= sc0; accO[n][1] *= sc0;
            accO[n][2] *= sc1; accO[n][3] *= sc1;
        }
        ps0 += __shfl_xor_sync(0xffffffffu, ps0, 1);
        ps0 += __shfl_xor_sync(0xffffffffu, ps0, 2);
        ps1 += __shfl_xor_sync(0xffffffffu, ps1, 1);
        ps1 += __shfl_xor_sync(0xffffffffu, ps1, 2);
        l0 = l0 * sc0 + ps0;
        l1 = l1 * sc1 + ps1;
        m0 = mn0; m1 = mn1;

        // O += P V : A = {pp0[2k], pp1[2k], pp0[2k+1], pp1[2k+1]} per k-step
#pragma unroll
        for (int k = 0; k < 4; k++) {
#pragma unroll
            for (int n2 = 0; n2 < 4; n2++) {
                uint4 bb = V4[(k * 4 + n2) * 32 + lane];
                mma_bf16(accO[2*n2][0], accO[2*n2][1], accO[2*n2][2], accO[2*n2][3],
                         pp0[2*k], pp1[2*k], pp0[2*k+1], pp1[2*k+1], bb.x, bb.y);
                mma_bf16(accO[2*n2+1][0], accO[2*n2+1][1], accO[2*n2+1][2], accO[2*n2+1][3],
                         pp0[2*k], pp1[2*k], pp0[2*k+1], pp1[2*k+1], bb.z, bb.w);
            }
        }
        __syncthreads();  // stage cur may be overwritten next iteration
        cur ^= 1;
    }

    // epilogue: normalize, write bf16 (oproj raw-copies it)
    float inv0 = 1.f / l0, inv1 = 1.f / l1;
    int row0 = i0 + wr + g, row1 = row0 + 8;
#pragma unroll
    for (int n = 0; n < 8; n++) {
        int col = h * 64 + n * 8 + 2 * t;
        unsigned o0 = packbf(accO[n][0] * inv0, accO[n][1] * inv0);
        unsigned o1 = packbf(accO[n][2] * inv1, accO[n][3] * inv1);
        *reinterpret_cast<unsigned*>(&g_aoh[(size_t)(b * S_ + row0) * NV + col]) = o0;
        *reinterpret_cast<unsigned*>(&g_aoh[(size_t)(b * S_ + row1) * NV + col]) = o1;
    }
}

// ---------------------------------------------------------------------------
// LN stats reduce + finalize
// ---------------------------------------------------------------------------
__global__ void stats_reduce()
{
    int w = threadIdx.x >> 5, lane = threadIdx.x & 31;
    float s = g_psum[w * 64 + lane] + g_psum[w * 64 + 32 + lane];
    float q = g_psq [w * 64 + lane] + g_psq [w * 64 + 32 + lane];
#pragma unroll
    for (int off = 16; off > 0; off >>= 1) {
        s += __shfl_down_sync(0xffffffffu, s, off);
        q += __shfl_down_sync(0xffffffffu, q, off);
    }
    if (lane == 0) { g_stats[2 * w] = s; g_stats[2 * w + 1] = q; }
}

__global__ void ln_finalize(float* __restrict__ y,
                            const float* __restrict__ lnw,
                            const float* __restrict__ lnb)
{
    int idx = blockIdx.x * 256 + threadIdx.x;
    int b   = idx >> 18;
    int sd4 = idx & ((1 << 18) - 1);
    const float invn = 1.0f / 1048576.0f;
    float mean = g_stats[2 * b] * invn;
    float var  = g_stats[2 * b + 1] * invn - mean * mean;
    float inv  = rsqrtf(var + 1e-5f);
    float4 v  = reinterpret_cast<float4*>(y)[idx];
    float4 w  = reinterpret_cast<const float4*>(lnw)[sd4];
    float4 bb = reinterpret_cast<const float4*>(lnb)[sd4];
    v.x = (v.x - mean) * inv * w.x + bb.x;
    v.y = (v.y - mean) * inv * w.y + bb.y;
    v.z = (v.z - mean) * inv * w.z + bb.z;
    v.w = (v.w - mean) * inv * w.w + bb.w;
    reinterpret_cast<float4*>(y)[idx] = v;
}

// ---------------------------------------------------------------------------
// kernel_launch
// ---------------------------------------------------------------------------
extern "C" void kernel_launch(void* const* d_in, const int* in_sizes, int n_in,
                              void* d_out, int out_size)
{
    const float* x    = (const float*)d_in[0];
    const float* W_qk = (const float*)d_in[1];
    const float* b_qk = (const float*)d_in[2];
    const float* W_v  = (const float*)d_in[3];
    const float* b_v  = (const float*)d_in[4];
    const float* W_o  = (const float*)d_in[5];
    const float* b_o  = (const float*)d_in[6];
    const float* ln_w = (const float*)d_in[7];
    const float* ln_b = (const float*)d_in[8];
    float* out = (float*)d_out;

    void *p_qk, *p_v, *p_aoh, *p_xh, *p_wqkh, *p_wvh, *p_woh;
    cudaGetSymbolAddress(&p_qk,   g_qk);
    cudaGetSymbolAddress(&p_v,    g_v);
    cudaGetSymbolAddress(&p_aoh,  g_aoh);
    cudaGetSymbolAddress(&p_xh,   g_xh);
    cudaGetSymbolAddress(&p_wqkh, g_wqkh);
    cudaGetSymbolAddress(&p_wvh,  g_wvh);
    cudaGetSymbolAddress(&p_woh,  g_woh);

    cudaFuncSetAttribute(attn_tc_kernel, cudaFuncAttributeMaxDynamicSharedMemorySize,
                         AT_SMEM_BYTES);

    // 0) bf16 packing of x + weights
    pack_bf16_kernel<<<(B_*S_*D_) / 1024, 256>>>((__nv_bfloat16*)p_xh,   x);
    pack_bf16_kernel<<<(NQK*D_)   / 1024, 256>>>((__nv_bfloat16*)p_wqkh, W_qk);
    pack_bf16_kernel<<<(NV*D_)    / 1024, 256>>>((__nv_bfloat16*)p_wvh,  W_v);
    pack_bf16_kernel<<<(D_*NV)    / 1024, 256>>>((__nv_bfloat16*)p_woh,  W_o);

    // 1) qk = x @ W_qk^T + b_qk   (8192 x 2048) — bf16 MMA
    hgemm_bias<<<dim3(NQK / 128, MROWS / 128), 256>>>((const __nv_bfloat16*)p_xh,
                                                      (const __nv_bfloat16*)p_wqkh, b_qk,
                                                      (float*)p_qk, NQK);
    // 2) v  = x @ W_v^T + b_v     (8192 x 1024) — bf16 MMA
    hgemm_bias<<<dim3(NV / 128, MROWS / 128), 256>>>((const __nv_bfloat16*)p_xh,
                                                     (const __nv_bfloat16*)p_wvh, b_v,
                                                     (float*)p_v, NV);
    // 3) repack: Q bf16 row-major (pre-scaled); K/V bf16 frag-major tiles
    repack_kernel<<<MROWS / 2, 256>>>();
    // 4) flash attention — bf16 MMA, register-resident P, cp.async pipeline
    attn_tc_kernel<<<dim3(S_ / 128, H_, B_), 256, AT_SMEM_BYTES>>>();
    // 5) O-proj (bf16 MMA) + bias + residual + partial LN stats
    hgemm_oproj<<<dim3(NV / 128, MROWS / 128), 256>>>((const __nv_bfloat16*)p_aoh,
                                                      (const __nv_bfloat16*)p_woh, b_o, x, out);
    // 6) reduce stats per batch
    stats_reduce<<<1, 256>>>();
    // 7) LayerNorm finalize
    ln_finalize<<<(B_ * S_ * D_ / 4) / 256, 256>>>(out, ln_w, ln_b);
}